// round 8
// baseline (speedup 1.0000x reference)
#include <cuda_runtime.h>
#include <cuda_bf16.h>
#include <cuda_fp16.h>
#include <math.h>
#include <stdint.h>

#define NN 4096
#define NE 8192
#define NGR 256
#define AF 9
#define BF 4
#define H  128
#define NL 3

#define NCOL (H * H)          // 16384
#define BM 128
#define BN 128
#define NBROWS (NCOL + H)
#define KA 256                // A2 row: [hi(128) | lo(128)]
#define KB 256
#define NSTRIP 9              // n-tile strips (129 tiles strided over 9 strips)

// ---------------- scratch ----------------
__device__ float g_h[NN * H];
__device__ float g_eh[NL * NE * H];
__device__ __half g_U[(size_t)NN * NCOL];
__device__ float g_nbias[NN * H];
__device__ float g_agg[NN * H];
__device__ float g_deg[NN];
__device__ float g_mol[NGR * H];
__device__ float g_cnt[NGR];
__device__ __align__(16) __nv_bfloat16 g_A2[(size_t)NN * KA];
__device__ __align__(16) __nv_bfloat16 g_B2[(size_t)NL * NBROWS * KB];
__device__ int g_hist[NN];
__device__ int g_base[NN];
__device__ int g_cnt2[NN];
__device__ int g_perm[NE];

__device__ __forceinline__ float gelu_exact(float x) {
    return 0.5f * x * (1.0f + erff(x * 0.70710678118654752440f));
}
__device__ __forceinline__ uint32_t smem_u32(const void* p) {
    uint32_t a;
    asm("{ .reg .u64 t; cvta.to.shared.u64 t, %1; cvt.u32.u64 %0, t; }" : "=r"(a) : "l"(p));
    return a;
}

// ---------------- small kernels ----------------
__global__ void k_zero() {
    int i = blockIdx.x * blockDim.x + threadIdx.x;
    if (i < NN * H) g_agg[i] = 0.f;
    if (i < NN) { g_deg[i] = 0.f; g_hist[i] = 0; g_cnt2[i] = 0; }
    if (i < NGR * H) g_mol[i] = 0.f;
    if (i < NGR) g_cnt[i] = 0.f;
}
__global__ void k_deghist(const int* __restrict__ ei) {
    int e = blockIdx.x * blockDim.x + threadIdx.x;
    if (e < NE) {
        atomicAdd(&g_deg[ei[NE + e]], 1.0f);
        atomicAdd(&g_hist[ei[e]], 1);
    }
}
__global__ void k_scan() {
    __shared__ int ws[128];
    int t = threadIdx.x;
    int s = 0;
#pragma unroll
    for (int i = 0; i < 32; i++) s += g_hist[t * 32 + i];
    ws[t] = s;
    __syncthreads();
    if (t == 0) {
        int acc = 0;
        for (int i = 0; i < 128; i++) { int v = ws[i]; ws[i] = acc; acc += v; }
    }
    __syncthreads();
    int start = ws[t];
    s = 0;
#pragma unroll
    for (int i = 0; i < 32; i++) {
        g_base[t * 32 + i] = start + s;
        s += g_hist[t * 32 + i];
    }
}
__global__ void k_scatter(const int* __restrict__ ei) {
    int e = blockIdx.x * blockDim.x + threadIdx.x;
    if (e < NE) {
        int src = ei[e];
        int pos = g_base[src] + atomicAdd(&g_cnt2[src], 1);
        g_perm[pos] = e;
    }
}

__global__ void k_atom_split(const float* __restrict__ x, const float* __restrict__ w,
                             const float* __restrict__ b) {
    int n = blockIdx.x, o = threadIdx.x;
    __shared__ float xs[AF];
    if (o < AF) xs[o] = x[n * AF + o];
    __syncthreads();
    float acc = b[o];
#pragma unroll
    for (int f = 0; f < AF; f++) acc += xs[f] * w[f * H + o];
    float v = fmaxf(acc, 0.f);
    g_h[n * H + o] = v;
    __nv_bfloat16 hi = __float2bfloat16(v);
    g_A2[(size_t)n * KA + o] = hi;
    g_A2[(size_t)n * KA + 128 + o] = __float2bfloat16(v - __bfloat162float(hi));
}

__global__ void k_edge3(const float* __restrict__ ea, const float* __restrict__ w1,
                        const float* __restrict__ b1) {
    int e = blockIdx.x, l = blockIdx.y, o = threadIdx.x;
    __shared__ float es[BF];
    if (o < BF) es[o] = ea[e * BF + o];
    __syncthreads();
    const float* w = w1 + (size_t)l * BF * H;
    float a = b1[l * H + o];
#pragma unroll
    for (int f = 0; f < BF; f++) a += es[f] * w[f * H + o];
    g_eh[(size_t)l * NE * H + e * H + o] = gelu_exact(a);
}

__global__ void k_permW3(const float* __restrict__ W2) {
    int rowg = blockIdx.x * 4 + (threadIdx.x >> 5);
    int lid = threadIdx.x & 31;
    int l = rowg / NCOL, row = rowg - l * NCOL;
    int m = row >> 7, o = row & 127;
    const float* src = W2 + (size_t)l * H * NCOL + (size_t)m * NCOL + o;
    size_t base = ((size_t)l * NBROWS + row) * KB;
#pragma unroll
    for (int t = 0; t < 4; t++) {
        int i = t * 32 + lid;
        float v = src[(size_t)i * H];
        __nv_bfloat16 hi = __float2bfloat16(v);
        g_B2[base + i] = hi;
        g_B2[base + 128 + i] = __float2bfloat16(v - __bfloat162float(hi));
    }
}
__global__ void k_permB3(const float* __restrict__ e2b) {
    int og = blockIdx.x * 4 + (threadIdx.x >> 5);
    int lid = threadIdx.x & 31;
    int l = og / H, o = og - l * H;
    const float* Bb = e2b + (size_t)l * NCOL;
    size_t base = ((size_t)l * NBROWS + NCOL + o) * KB;
#pragma unroll
    for (int t = 0; t < 4; t++) {
        int i = t * 32 + lid;
        float v = Bb[(size_t)i * H + o];
        __nv_bfloat16 hi = __float2bfloat16(v);
        g_B2[base + i] = hi;
        g_B2[base + 128 + i] = __float2bfloat16(v - __bfloat162float(hi));
    }
}

// ---------------- persistent-strip HMMA GEMM ----------------
// A resident: slots 0..3 (Ah0,Ah1,Al0,Al1) @ sm + slot*16KB (64KB total).
// B ring: 3 x 16KB @ smB. Each CTA = (mtile, strip); tiles nt = strip + 9*i.
// Per tile chunk stream [Bh0,Bh1,Bl0,Bl1]; passes:
//   c0:(Ah0,Al0)  c1:(Ah1,Al1)  c2:(Ah0)  c3:(Ah1)
#define SW(row, kb) (((row) * 128 + (kb)) ^ (((row) & 7) << 4))

#define LOAD_CHUNK(dstbase, gsrc)                                                    \
    {                                                                                \
        _Pragma("unroll")                                                            \
        for (int i_ = 0; i_ < 8; i_++) {                                             \
            int cidx = tid + i_ * 128;                                               \
            int row = cidx >> 3, kc = cidx & 7;                                      \
            const void* src = (const char*)(gsrc) + (size_t)row * 512 + kc * 16;     \
            asm volatile("cp.async.cg.shared.global [%0], [%1], 16;" ::              \
                         "r"((dstbase) + SW(row, kc * 16)), "l"(src));               \
        }                                                                            \
    }
#define COMMIT() asm volatile("cp.async.commit_group;")
#define WAIT2() { asm volatile("cp.async.wait_group 2;"); __syncthreads(); }

#define COMPUTE(aoff, boff)                                                          \
    {                                                                                \
        const uint32_t aB = sm + (aoff), bB = smB + (boff);                          \
        _Pragma("unroll")                                                            \
        for (int ks = 0; ks < 4; ks++) {                                             \
            uint32_t a[4][4];                                                        \
            _Pragma("unroll")                                                        \
            for (int mt = 0; mt < 4; mt++) {                                         \
                int row = wm * 64 + mt * 16 + (lane & 15);                           \
                int kb = ks * 32 + (lane >> 4) * 16;                                 \
                asm volatile("ldmatrix.sync.aligned.m8n8.x4.shared.b16 {%0,%1,%2,%3}, [%4];" \
                             : "=r"(a[mt][0]), "=r"(a[mt][1]), "=r"(a[mt][2]), "=r"(a[mt][3]) \
                             : "r"(aB + SW(row, kb)));                               \
            }                                                                        \
            uint32_t b[4][4];                                                        \
            _Pragma("unroll")                                                        \
            for (int bt = 0; bt < 4; bt++) {                                         \
                int nrow = wn * 64 + bt * 16 + (lane & 7) + ((lane >> 4) & 1) * 8;   \
                int kb = ks * 32 + ((lane >> 3) & 1) * 16;                           \
                asm volatile("ldmatrix.sync.aligned.m8n8.x4.shared.b16 {%0,%1,%2,%3}, [%4];" \
                             : "=r"(b[bt][0]), "=r"(b[bt][1]), "=r"(b[bt][2]), "=r"(b[bt][3]) \
                             : "r"(bB + SW(nrow, kb)));                              \
            }                                                                        \
            _Pragma("unroll")                                                        \
            for (int mt = 0; mt < 4; mt++) {                                         \
                _Pragma("unroll")                                                    \
                for (int nt = 0; nt < 8; nt++) {                                     \
                    asm volatile(                                                    \
                        "mma.sync.aligned.m16n8k16.row.col.f32.bf16.bf16.f32 "       \
                        "{%0,%1,%2,%3}, {%4,%5,%6,%7}, {%8,%9}, {%0,%1,%2,%3};"      \
                        : "+f"(c[mt][nt][0]), "+f"(c[mt][nt][1]),                    \
                          "+f"(c[mt][nt][2]), "+f"(c[mt][nt][3])                     \
                        : "r"(a[mt][0]), "r"(a[mt][1]), "r"(a[mt][2]), "r"(a[mt][3]), \
                          "r"(b[nt >> 1][(nt & 1) * 2]), "r"(b[nt >> 1][(nt & 1) * 2 + 1])); \
                }                                                                    \
            }                                                                        \
        }                                                                            \
    }

__global__ __launch_bounds__(128, 2) void k_U_mma(int l) {
    extern __shared__ char smem[];
    const int tid = threadIdx.x;
    const int warp = tid >> 5, lane = tid & 31;
    const int wm = warp >> 1, wn = warp & 1;
    const int mtile = blockIdx.x, strip = blockIdx.y;
    const uint32_t sm = smem_u32(smem);
    const uint32_t smB = sm + 65536;

    const char* gA = (const char*)(g_A2 + (size_t)mtile * BM * KA);
    const char* gBbase = (const char*)(g_B2 + (size_t)l * NBROWS * KB);

    const int ntiles = (128 - strip) / NSTRIP + 1;   // tiles nt = strip + 9*i, nt <= 128
    const int totalchunks = ntiles * 4;

    // prologue: A (one group) then 3 B chunks (one group each)
    LOAD_CHUNK(sm + 0,     gA + 0);
    LOAD_CHUNK(sm + 16384, gA + 128);
    LOAD_CHUNK(sm + 32768, gA + 256);
    LOAD_CHUNK(sm + 49152, gA + 384);
    COMMIT();

    int pk = 0;   // next chunk index to prefetch
#define PREFETCH(slot)                                                               \
    {                                                                                \
        if (pk < totalchunks) {                                                      \
            int ti_ = pk >> 2, c_ = pk & 3;                                          \
            int ntp_ = strip + ti_ * NSTRIP;                                         \
            const char* gsrc_ = gBbase + (size_t)ntp_ * (128 * 512) + c_ * 128;      \
            LOAD_CHUNK(smB + (slot) * 16384, gsrc_);                                 \
        }                                                                            \
        COMMIT();                                                                    \
        pk++;                                                                        \
    }

    PREFETCH(0); PREFETCH(1); PREFETCH(2);
    int qs = 0;   // ring slot of next chunk to consume

    for (int i = 0; i < ntiles; i++) {
        const int ntile = strip + i * NSTRIP;
        float c[4][8][4];
#pragma unroll
        for (int mt = 0; mt < 4; mt++)
#pragma unroll
            for (int nt = 0; nt < 8; nt++)
#pragma unroll
                for (int k = 0; k < 4; k++) c[mt][nt][k] = 0.f;

        // c0 = Bh0: Ah0, Al0
        WAIT2(); COMPUTE(0, qs * 16384); COMPUTE(32768, qs * 16384);
        __syncthreads(); PREFETCH(qs); qs = (qs + 1) % 3;
        // c1 = Bh1: Ah1, Al1
        WAIT2(); COMPUTE(16384, qs * 16384); COMPUTE(49152, qs * 16384);
        __syncthreads(); PREFETCH(qs); qs = (qs + 1) % 3;
        // c2 = Bl0: Ah0
        WAIT2(); COMPUTE(0, qs * 16384);
        __syncthreads(); PREFETCH(qs); qs = (qs + 1) % 3;
        // c3 = Bl1: Ah1
        WAIT2(); COMPUTE(16384, qs * 16384);
        __syncthreads(); PREFETCH(qs); qs = (qs + 1) % 3;

        // epilogue for this tile
        if (ntile < NCOL / BN) {
            const int n0 = ntile * BN;
#pragma unroll
            for (int mt = 0; mt < 4; mt++) {
                int r0 = mtile * BM + wm * 64 + mt * 16 + (lane >> 2);
#pragma unroll
                for (int nt = 0; nt < 8; nt++) {
                    int col = n0 + wn * 64 + nt * 8 + (lane & 3) * 2;
                    *(__half2*)(g_U + (size_t)r0 * NCOL + col) =
                        __floats2half2_rn(c[mt][nt][0], c[mt][nt][1]);
                    *(__half2*)(g_U + (size_t)(r0 + 8) * NCOL + col) =
                        __floats2half2_rn(c[mt][nt][2], c[mt][nt][3]);
                }
            }
        } else {
#pragma unroll
            for (int mt = 0; mt < 4; mt++) {
                int r0 = mtile * BM + wm * 64 + mt * 16 + (lane >> 2);
#pragma unroll
                for (int nt = 0; nt < 8; nt++) {
                    int col = wn * 64 + nt * 8 + (lane & 3) * 2;
                    *(float2*)(g_nbias + (size_t)r0 * H + col) = make_float2(c[mt][nt][0], c[mt][nt][1]);
                    *(float2*)(g_nbias + (size_t)(r0 + 8) * H + col) = make_float2(c[mt][nt][2], c[mt][nt][3]);
                }
            }
        }
    }
}
#define GEMM_SMEM (65536 + 3 * 16384)

// per-src-node msg
__global__ __launch_bounds__(128) void k_msg(const int* __restrict__ ei, int l) {
    int n = blockIdx.x;
    int cnt = g_hist[n];
    if (cnt == 0) return;
    int base = g_base[n];
    int o = threadIdx.x;
    __shared__ float es[4][H];
    __shared__ int dsts[4];
    const float* ehL = g_eh + (size_t)l * NE * H;
    float nb = g_nbias[n * H + o];
    const __half* __restrict__ Up = g_U + (size_t)n * NCOL + o;
    for (int g0 = 0; g0 < cnt; g0 += 4) {
        int ng = min(4, cnt - g0);
#pragma unroll
        for (int k = 0; k < 4; k++) {
            if (k < ng) {
                int e = g_perm[base + g0 + k];
                es[k][o] = ehL[(size_t)e * H + o];
                if (o == 0) dsts[k] = ei[NE + e];
            } else {
                es[k][o] = 0.f;
            }
        }
        __syncthreads();
        float a0 = 0.f, a1 = 0.f, a2 = 0.f, a3 = 0.f;
#pragma unroll 4
        for (int j = 0; j < H; j++) {
            float u = __half2float(Up[j * H]);
            a0 += es[0][j] * u;
            a1 += es[1][j] * u;
            a2 += es[2][j] * u;
            a3 += es[3][j] * u;
        }
        atomicAdd(&g_agg[dsts[0] * H + o], a0 + nb);
        if (1 < ng) atomicAdd(&g_agg[dsts[1] * H + o], a1 + nb);
        if (2 < ng) atomicAdd(&g_agg[dsts[2] * H + o], a2 + nb);
        if (3 < ng) atomicAdd(&g_agg[dsts[3] * H + o], a3 + nb);
        __syncthreads();
    }
}

// update + A2 split + agg reset, fused
__global__ void k_update(const float* __restrict__ rootw, const float* __restrict__ convb,
                         const float* __restrict__ lng, const float* __restrict__ lnb) {
    int n = blockIdx.x, o = threadIdx.x;
    __shared__ float hs[H];
    __shared__ float sa[4], sb2[4];
    float hval = g_h[n * H + o];
    hs[o] = hval;
    __syncthreads();
    float r = convb[o];
#pragma unroll 8
    for (int i = 0; i < H; i++) r += hs[i] * rootw[i * H + o];
    float denom = fmaxf(g_deg[n], 1.0f);
    float hn = fmaxf(g_agg[n * H + o] / denom + r, 0.f);
    g_agg[n * H + o] = 0.f;
    float y = hval + hn;

    float s = y, s2 = y * y;
#pragma unroll
    for (int sh = 16; sh > 0; sh >>= 1) {
        s  += __shfl_xor_sync(0xffffffffu, s, sh);
        s2 += __shfl_xor_sync(0xffffffffu, s2, sh);
    }
    int w = o >> 5;
    if ((o & 31) == 0) { sa[w] = s; sb2[w] = s2; }
    __syncthreads();
    float ts = sa[0] + sa[1] + sa[2] + sa[3];
    float ts2 = sb2[0] + sb2[1] + sb2[2] + sb2[3];
    float mu = ts * (1.0f / H);
    float var = ts2 * (1.0f / H) - mu * mu;
    float inv = rsqrtf(var + 1e-5f);
    float v = (y - mu) * inv * lng[o] + lnb[o];
    g_h[n * H + o] = v;
    __nv_bfloat16 hi = __float2bfloat16(v);
    g_A2[(size_t)n * KA + o] = hi;
    g_A2[(size_t)n * KA + 128 + o] = __float2bfloat16(v - __bfloat162float(hi));
}

__global__ void k_pool(const int* __restrict__ batch) {
    int n = blockIdx.x, o = threadIdx.x;
    int b = batch[n];
    atomicAdd(&g_mol[b * H + o], g_h[n * H + o]);
    if (o == 0) atomicAdd(&g_cnt[b], 1.0f);
}

__global__ void k_head(const float* __restrict__ w1, const float* __restrict__ b1,
                       const float* __restrict__ w2, const float* __restrict__ b2,
                       float* __restrict__ out) {
    int g = blockIdx.x, t = threadIdx.x;
    __shared__ float ms[H];
    __shared__ float part[2];
    float inv = 1.0f / fmaxf(g_cnt[g], 1.0f);
    ms[t]      = g_mol[g * H + t] * inv;
    ms[t + 64] = g_mol[g * H + t + 64] * inv;
    __syncthreads();
    float a = b1[t];
#pragma unroll 8
    for (int i = 0; i < H; i++) a += ms[i] * w1[i * 64 + t];
    float v = gelu_exact(a) * w2[t];
#pragma unroll
    for (int sh = 16; sh > 0; sh >>= 1) v += __shfl_xor_sync(0xffffffffu, v, sh);
    if ((t & 31) == 0) part[t >> 5] = v;
    __syncthreads();
    if (t == 0) out[g] = part[0] + part[1] + b2[0];
}

// ---------------- launch ----------------
extern "C" void kernel_launch(void* const* d_in, const int* in_sizes, int n_in,
                              void* d_out, int out_size) {
    const float* x        = (const float*)d_in[0];
    const int*   ei       = (const int*)  d_in[1];
    const float* ea       = (const float*)d_in[2];
    const int*   batch    = (const int*)  d_in[3];
    const float* atom_w   = (const float*)d_in[4];
    const float* atom_b   = (const float*)d_in[5];
    const float* e1_w     = (const float*)d_in[6];
    const float* e1_b     = (const float*)d_in[7];
    const float* e2_w     = (const float*)d_in[8];
    const float* e2_b     = (const float*)d_in[9];
    const float* root_w   = (const float*)d_in[10];
    const float* conv_b   = (const float*)d_in[11];
    const float* ln_g     = (const float*)d_in[12];
    const float* ln_b     = (const float*)d_in[13];
    const float* head_w1  = (const float*)d_in[14];
    const float* head_b1  = (const float*)d_in[15];
    const float* head_w2  = (const float*)d_in[16];
    const float* head_b2  = (const float*)d_in[17];
    float* out = (float*)d_out;

    cudaFuncSetAttribute(k_U_mma, cudaFuncAttributeMaxDynamicSharedMemorySize, GEMM_SMEM);

    dim3 gemm_grid(NN / BM, NSTRIP);

    // launch index 3 (the ncu capture slot) = layer-0 GEMM
    k_permB3<<<NL * H / 4, 128>>>(e2_b);                                    // 0
    k_permW3<<<NL * NCOL / 4, 128>>>(e2_w);                                 // 1
    k_atom_split<<<NN, H>>>(x, atom_w, atom_b);                             // 2
    k_U_mma<<<gemm_grid, 128, GEMM_SMEM>>>(0);                              // 3 <- profiled
    k_edge3<<<dim3(NE, NL), H>>>(ea, e1_w, e1_b);                           // 4
    k_zero<<<(NN * H + 255) / 256, 256>>>();                                // 5
    k_deghist<<<(NE + 255) / 256, 256>>>(ei);                               // 6
    k_scan<<<1, 128>>>();                                                   // 7
    k_scatter<<<(NE + 255) / 256, 256>>>(ei);                               // 8
    k_msg<<<NN, 128>>>(ei, 0);                                              // 9
    k_update<<<NN, H>>>(root_w, conv_b, ln_g, ln_b);                        // 10

    for (int l = 1; l < NL; l++) {
        k_U_mma<<<gemm_grid, 128, GEMM_SMEM>>>(l);
        k_msg<<<NN, 128>>>(ei, l);
        k_update<<<NN, H>>>(root_w + (size_t)l * H * H, conv_b + (size_t)l * H,
                            ln_g + (size_t)l * H, ln_b + (size_t)l * H);
    }

    k_pool<<<NN, H>>>(batch);
    k_head<<<NGR, 64>>>(head_w1, head_b1, head_w2, head_b2, out);
}

// round 9
// speedup vs baseline: 1.1868x; 1.1868x over previous
#include <cuda_runtime.h>
#include <cuda_bf16.h>
#include <cuda_fp16.h>
#include <math.h>
#include <stdint.h>

#define NN 4096
#define NE 8192
#define NGR 256
#define AF 9
#define BF 4
#define H  128
#define NL 3

#define NCOL (H * H)          // 16384
#define BM 128
#define BN 128
#define NBROWS (NCOL + H)
#define KA 256                // A2 row: [hi(128) | lo(128)]
#define KB 256

// ---------------- scratch ----------------
__device__ float g_h[NN * H];
__device__ float g_eh[NL * NE * H];
__device__ __half g_U[(size_t)NN * NCOL];
__device__ float g_nbias[NN * H];
__device__ float g_agg[NN * H];
__device__ float g_deg[NN];
__device__ float g_mol[NGR * H];
__device__ float g_cnt[NGR];
__device__ __align__(16) __nv_bfloat16 g_A2[(size_t)NN * KA];
__device__ __align__(16) __nv_bfloat16 g_B2[(size_t)NL * NBROWS * KB];
__device__ int g_hist[NN];
__device__ int g_base[NN];
__device__ int g_perm[NE];

__device__ __forceinline__ float gelu_exact(float x) {
    return 0.5f * x * (1.0f + erff(x * 0.70710678118654752440f));
}
__device__ __forceinline__ uint32_t smem_u32(const void* p) {
    uint32_t a;
    asm("{ .reg .u64 t; cvta.to.shared.u64 t, %1; cvt.u32.u64 %0, t; }" : "=r"(a) : "l"(p));
    return a;
}

// ---------------- prep: deg + hist + scan + scatter, one block ----------------
__global__ __launch_bounds__(1024) void k_prep(const int* __restrict__ ei) {
    __shared__ int cur[NN];          // 16 KB
    __shared__ int wsum[32];
    const int t = threadIdx.x;
    for (int n = t; n < NN; n += 1024) { cur[n] = 0; g_deg[n] = 0.f; }
    __syncthreads();
    for (int e = t; e < NE; e += 1024) {
        atomicAdd(&cur[ei[e]], 1);
        atomicAdd(&g_deg[ei[NE + e]], 1.0f);
    }
    __syncthreads();
    const int c0 = cur[4 * t], c1 = cur[4 * t + 1], c2 = cur[4 * t + 2], c3 = cur[4 * t + 3];
    const int s = c0 + c1 + c2 + c3;
    const int lane = t & 31, wid = t >> 5;
    int sc = s;
#pragma unroll
    for (int d = 1; d < 32; d <<= 1) {
        int v = __shfl_up_sync(0xffffffffu, sc, d);
        if (lane >= d) sc += v;
    }
    if (lane == 31) wsum[wid] = sc;
    __syncthreads();
    if (wid == 0) {
        int v = wsum[lane];
#pragma unroll
        for (int d = 1; d < 32; d <<= 1) {
            int u = __shfl_up_sync(0xffffffffu, v, d);
            if (lane >= d) v += u;
        }
        wsum[lane] = v;
    }
    __syncthreads();
    const int excl = sc - s + (wid ? wsum[wid - 1] : 0);
    g_hist[4 * t] = c0; g_hist[4 * t + 1] = c1; g_hist[4 * t + 2] = c2; g_hist[4 * t + 3] = c3;
    const int b0 = excl, b1 = b0 + c0, b2 = b1 + c1, b3 = b2 + c2;
    g_base[4 * t] = b0; g_base[4 * t + 1] = b1; g_base[4 * t + 2] = b2; g_base[4 * t + 3] = b3;
    __syncthreads();
    cur[4 * t] = b0; cur[4 * t + 1] = b1; cur[4 * t + 2] = b2; cur[4 * t + 3] = b3;
    __syncthreads();
    for (int e = t; e < NE; e += 1024) {
        int pos = atomicAdd(&cur[ei[e]], 1);
        g_perm[pos] = e;
    }
}

// atom embed + split + zero agg/mol/cnt
__global__ void k_atom_split(const float* __restrict__ x, const float* __restrict__ w,
                             const float* __restrict__ b) {
    int n = blockIdx.x, o = threadIdx.x;
    __shared__ float xs[AF];
    if (o < AF) xs[o] = x[n * AF + o];
    g_agg[n * H + o] = 0.f;
    if (n < NGR) g_mol[n * H + o] = 0.f;
    if (n < 2) g_cnt[n * H + o] = 0.f;
    __syncthreads();
    float acc = b[o];
#pragma unroll
    for (int f = 0; f < AF; f++) acc += xs[f] * w[f * H + o];
    float v = fmaxf(acc, 0.f);
    g_h[n * H + o] = v;
    __nv_bfloat16 hi = __float2bfloat16(v);
    g_A2[(size_t)n * KA + o] = hi;
    g_A2[(size_t)n * KA + 128 + o] = __float2bfloat16(v - __bfloat162float(hi));
}

__global__ void k_edge3(const float* __restrict__ ea, const float* __restrict__ w1,
                        const float* __restrict__ b1) {
    int e = blockIdx.x, l = blockIdx.y, o = threadIdx.x;
    __shared__ float es[BF];
    if (o < BF) es[o] = ea[e * BF + o];
    __syncthreads();
    const float* w = w1 + (size_t)l * BF * H;
    float a = b1[l * H + o];
#pragma unroll
    for (int f = 0; f < BF; f++) a += es[f] * w[f * H + o];
    g_eh[(size_t)l * NE * H + e * H + o] = gelu_exact(a);
}

// W2 permute+split via SMEM transpose. One block per (l,j): 128x128 fp32 tile.
__global__ __launch_bounds__(256) void k_permW3t(const float* __restrict__ W2) {
    extern __shared__ float ts[];  // [128][129]
    int bj = blockIdx.x;
    int l = bj >> 7, j = bj & 127;
    const float* src = W2 + ((size_t)l * H + j) * NCOL;  // contiguous 16384 floats
    int tid = threadIdx.x;
    for (int idx = tid; idx < H * H; idx += 256) {
        int i = idx >> 7, o = idx & 127;
        ts[i * 129 + o] = src[idx];
    }
    __syncthreads();
    size_t rowbase = ((size_t)l * NBROWS + (size_t)j * H) * KB;
    for (int idx = tid; idx < H * H; idx += 256) {
        int o = idx >> 7, i = idx & 127;
        float v = ts[i * 129 + o];
        __nv_bfloat16 hi = __float2bfloat16(v);
        g_B2[rowbase + (size_t)o * KB + i] = hi;
        g_B2[rowbase + (size_t)o * KB + 128 + i] = __float2bfloat16(v - __bfloat162float(hi));
    }
}
#define PERMW_SMEM (128 * 129 * 4)

__global__ void k_permB3(const float* __restrict__ e2b) {
    int og = blockIdx.x * 4 + (threadIdx.x >> 5);
    int lid = threadIdx.x & 31;
    int l = og / H, o = og - l * H;
    const float* Bb = e2b + (size_t)l * NCOL;
    size_t base = ((size_t)l * NBROWS + NCOL + o) * KB;
#pragma unroll
    for (int t = 0; t < 4; t++) {
        int i = t * 32 + lid;
        float v = Bb[(size_t)i * H + o];
        __nv_bfloat16 hi = __float2bfloat16(v);
        g_B2[base + i] = hi;
        g_B2[base + 128 + i] = __float2bfloat16(v - __bfloat162float(hi));
    }
}

// ---------------- HMMA GEMM (R7 proven config): 4 warps, 64x64 warp tile ----------------
#define SW(row, kb) (((row) * 128 + (kb)) ^ (((row) & 7) << 4))

#define LOAD_TILE(slot, gbase, coloff)                                               \
    {                                                                                \
        _Pragma("unroll")                                                            \
        for (int i_ = 0; i_ < 8; i_++) {                                             \
            int cidx = tid + i_ * 128;                                               \
            int row = cidx >> 3, kc = cidx & 7;                                      \
            const void* src = (const char*)(gbase) + (size_t)row * 512 + (coloff) + kc * 16; \
            asm volatile("cp.async.cg.shared.global [%0], [%1], 16;" ::              \
                         "r"(sm + (slot) * 16384 + SW(row, kc * 16)), "l"(src));     \
        }                                                                            \
    }
#define COMMIT() asm volatile("cp.async.commit_group;")
#define WAITSYNC(n) { asm volatile("cp.async.wait_group %0;" :: "n"(n)); __syncthreads(); }

#define COMPUTE(aslot, bslot)                                                        \
    {                                                                                \
        const uint32_t aB = sm + (aslot) * 16384, bB = sm + (bslot) * 16384;         \
        _Pragma("unroll")                                                            \
        for (int ks = 0; ks < 4; ks++) {                                             \
            uint32_t a[4][4];                                                        \
            _Pragma("unroll")                                                        \
            for (int mt = 0; mt < 4; mt++) {                                         \
                int row = wm * 64 + mt * 16 + (lane & 15);                           \
                int kb = ks * 32 + (lane >> 4) * 16;                                 \
                asm volatile("ldmatrix.sync.aligned.m8n8.x4.shared.b16 {%0,%1,%2,%3}, [%4];" \
                             : "=r"(a[mt][0]), "=r"(a[mt][1]), "=r"(a[mt][2]), "=r"(a[mt][3]) \
                             : "r"(aB + SW(row, kb)));                               \
            }                                                                        \
            uint32_t b[4][4];                                                        \
            _Pragma("unroll")                                                        \
            for (int bt = 0; bt < 4; bt++) {                                         \
                int nrow = wn * 64 + bt * 16 + (lane & 7) + ((lane >> 4) & 1) * 8;   \
                int kb = ks * 32 + ((lane >> 3) & 1) * 16;                           \
                asm volatile("ldmatrix.sync.aligned.m8n8.x4.shared.b16 {%0,%1,%2,%3}, [%4];" \
                             : "=r"(b[bt][0]), "=r"(b[bt][1]), "=r"(b[bt][2]), "=r"(b[bt][3]) \
                             : "r"(bB + SW(nrow, kb)));                              \
            }                                                                        \
            _Pragma("unroll")                                                        \
            for (int mt = 0; mt < 4; mt++) {                                         \
                _Pragma("unroll")                                                    \
                for (int nt = 0; nt < 8; nt++) {                                     \
                    asm volatile(                                                    \
                        "mma.sync.aligned.m16n8k16.row.col.f32.bf16.bf16.f32 "       \
                        "{%0,%1,%2,%3}, {%4,%5,%6,%7}, {%8,%9}, {%0,%1,%2,%3};"      \
                        : "+f"(c[mt][nt][0]), "+f"(c[mt][nt][1]),                    \
                          "+f"(c[mt][nt][2]), "+f"(c[mt][nt][3])                     \
                        : "r"(a[mt][0]), "r"(a[mt][1]), "r"(a[mt][2]), "r"(a[mt][3]), \
                          "r"(b[nt >> 1][(nt & 1) * 2]), "r"(b[nt >> 1][(nt & 1) * 2 + 1])); \
                }                                                                    \
            }                                                                        \
        }                                                                            \
    }

__global__ __launch_bounds__(128, 2) void k_U_mma(int l) {
    extern __shared__ char smem[];
    const int tid = threadIdx.x;
    const int warp = tid >> 5, lane = tid & 31;
    const int wm = warp >> 1, wn = warp & 1;
    const int m0 = blockIdx.x * BM;
    const int n0 = blockIdx.y * BN;
    const uint32_t sm = smem_u32(smem);

    float c[4][8][4];
#pragma unroll
    for (int mt = 0; mt < 4; mt++)
#pragma unroll
        for (int nt = 0; nt < 8; nt++)
#pragma unroll
            for (int k = 0; k < 4; k++) c[mt][nt][k] = 0.f;

    const char* gA = (const char*)(g_A2 + (size_t)m0 * KA);
    const char* gB = (const char*)(g_B2 + ((size_t)l * NBROWS + n0) * KB);

    LOAD_TILE(0, gA, 0);   LOAD_TILE(2, gB, 0);   COMMIT();
    LOAD_TILE(1, gA, 128); LOAD_TILE(3, gB, 128); COMMIT();
    LOAD_TILE(4, gA, 256);                        COMMIT();
    LOAD_TILE(5, gA, 384);                        COMMIT();

    WAITSYNC(3); COMPUTE(0, 2);        // Ah0*Bh0
    WAITSYNC(2); COMPUTE(1, 3);        // Ah1*Bh1
    WAITSYNC(1); COMPUTE(4, 2);        // Al0*Bh0
    __syncthreads();
    LOAD_TILE(4, gB, 256); COMMIT();   // Bl0->X0
    WAITSYNC(1); COMPUTE(5, 3);        // Al1*Bh1
    __syncthreads();
    LOAD_TILE(5, gB, 384); COMMIT();   // Bl1->X1
    WAITSYNC(1); COMPUTE(0, 4);        // Ah0*Bl0
    WAITSYNC(0); COMPUTE(1, 5);        // Ah1*Bl1

    if (blockIdx.y < NCOL / BN) {
#pragma unroll
        for (int mt = 0; mt < 4; mt++) {
            int r0 = m0 + wm * 64 + mt * 16 + (lane >> 2);
#pragma unroll
            for (int nt = 0; nt < 8; nt++) {
                int col = n0 + wn * 64 + nt * 8 + (lane & 3) * 2;
                *(__half2*)(g_U + (size_t)r0 * NCOL + col) =
                    __floats2half2_rn(c[mt][nt][0], c[mt][nt][1]);
                *(__half2*)(g_U + (size_t)(r0 + 8) * NCOL + col) =
                    __floats2half2_rn(c[mt][nt][2], c[mt][nt][3]);
            }
        }
    } else {
#pragma unroll
        for (int mt = 0; mt < 4; mt++) {
            int r0 = m0 + wm * 64 + mt * 16 + (lane >> 2);
#pragma unroll
            for (int nt = 0; nt < 8; nt++) {
                int col = wn * 64 + nt * 8 + (lane & 3) * 2;
                *(float2*)(g_nbias + (size_t)r0 * H + col) = make_float2(c[mt][nt][0], c[mt][nt][1]);
                *(float2*)(g_nbias + (size_t)(r0 + 8) * H + col) = make_float2(c[mt][nt][2], c[mt][nt][3]);
            }
        }
    }
}
#define GEMM_SMEM 98304

// per-src-node msg: half2 loads, j-range split across thread halves
__global__ __launch_bounds__(128) void k_msg(const int* __restrict__ ei, int l) {
    int n = blockIdx.x;
    int cnt = g_hist[n];
    if (cnt == 0) return;
    int base = g_base[n];
    int o = threadIdx.x;
    int half = o >> 6, o2 = o & 63;
    __shared__ float es[4][H];
    __shared__ int dsts[4];
    __shared__ float2 red[4][64];
    const float* ehL = g_eh + (size_t)l * NE * H;
    const float2 nb = *(const float2*)(g_nbias + (size_t)n * H + 2 * o2);
    const __half2* __restrict__ Up2 = (const __half2*)(g_U + (size_t)n * NCOL);

    for (int g0 = 0; g0 < cnt; g0 += 4) {
        int ng = min(4, cnt - g0);
#pragma unroll
        for (int k = 0; k < 4; k++) {
            if (k < ng) {
                int e = g_perm[base + g0 + k];
                es[k][o] = ehL[(size_t)e * H + o];
                if (o == 0) dsts[k] = ei[NE + e];
            } else {
                es[k][o] = 0.f;
            }
        }
        __syncthreads();
        float ax0 = 0.f, ay0 = 0.f, ax1 = 0.f, ay1 = 0.f;
        float ax2 = 0.f, ay2 = 0.f, ax3 = 0.f, ay3 = 0.f;
        const int jb = half * 64;
#pragma unroll 4
        for (int jj = 0; jj < 64; jj++) {
            int j = jb + jj;
            float2 u = __half22float2(Up2[j * 64 + o2]);
            ax0 += es[0][j] * u.x; ay0 += es[0][j] * u.y;
            ax1 += es[1][j] * u.x; ay1 += es[1][j] * u.y;
            ax2 += es[2][j] * u.x; ay2 += es[2][j] * u.y;
            ax3 += es[3][j] * u.x; ay3 += es[3][j] * u.y;
        }
        if (half) {
            red[0][o2] = make_float2(ax0, ay0);
            red[1][o2] = make_float2(ax1, ay1);
            red[2][o2] = make_float2(ax2, ay2);
            red[3][o2] = make_float2(ax3, ay3);
        }
        __syncthreads();
        if (!half) {
            float axs[4] = {ax0, ax1, ax2, ax3};
            float ays[4] = {ay0, ay1, ay2, ay3};
#pragma unroll
            for (int k = 0; k < 4; k++) {
                if (k < ng) {
                    float2 r = red[k][o2];
                    atomicAdd(&g_agg[dsts[k] * H + 2 * o2],     axs[k] + r.x + nb.x);
                    atomicAdd(&g_agg[dsts[k] * H + 2 * o2 + 1], ays[k] + r.y + nb.y);
                }
            }
        }
        __syncthreads();
    }
}

// update + A2 split + agg reset, fused
__global__ void k_update(const float* __restrict__ rootw, const float* __restrict__ convb,
                         const float* __restrict__ lng, const float* __restrict__ lnb) {
    int n = blockIdx.x, o = threadIdx.x;
    __shared__ float hs[H];
    __shared__ float sa[4], sb2[4];
    float hval = g_h[n * H + o];
    hs[o] = hval;
    __syncthreads();
    float r = convb[o];
#pragma unroll 8
    for (int i = 0; i < H; i++) r += hs[i] * rootw[i * H + o];
    float denom = fmaxf(g_deg[n], 1.0f);
    float hn = fmaxf(g_agg[n * H + o] / denom + r, 0.f);
    g_agg[n * H + o] = 0.f;
    float y = hval + hn;

    float s = y, s2 = y * y;
#pragma unroll
    for (int sh = 16; sh > 0; sh >>= 1) {
        s  += __shfl_xor_sync(0xffffffffu, s, sh);
        s2 += __shfl_xor_sync(0xffffffffu, s2, sh);
    }
    int w = o >> 5;
    if ((o & 31) == 0) { sa[w] = s; sb2[w] = s2; }
    __syncthreads();
    float ts = sa[0] + sa[1] + sa[2] + sa[3];
    float ts2 = sb2[0] + sb2[1] + sb2[2] + sb2[3];
    float mu = ts * (1.0f / H);
    float var = ts2 * (1.0f / H) - mu * mu;
    float inv = rsqrtf(var + 1e-5f);
    float v = (y - mu) * inv * lng[o] + lnb[o];
    g_h[n * H + o] = v;
    __nv_bfloat16 hi = __float2bfloat16(v);
    g_A2[(size_t)n * KA + o] = hi;
    g_A2[(size_t)n * KA + 128 + o] = __float2bfloat16(v - __bfloat162float(hi));
}

__global__ void k_pool(const int* __restrict__ batch) {
    int n = blockIdx.x, o = threadIdx.x;
    int b = batch[n];
    atomicAdd(&g_mol[b * H + o], g_h[n * H + o]);
    if (o == 0) atomicAdd(&g_cnt[b], 1.0f);
}

__global__ void k_head(const float* __restrict__ w1, const float* __restrict__ b1,
                       const float* __restrict__ w2, const float* __restrict__ b2,
                       float* __restrict__ out) {
    int g = blockIdx.x, t = threadIdx.x;
    __shared__ float ms[H];
    __shared__ float part[2];
    float inv = 1.0f / fmaxf(g_cnt[g], 1.0f);
    ms[t]      = g_mol[g * H + t] * inv;
    ms[t + 64] = g_mol[g * H + t + 64] * inv;
    __syncthreads();
    float a = b1[t];
#pragma unroll 8
    for (int i = 0; i < H; i++) a += ms[i] * w1[i * 64 + t];
    float v = gelu_exact(a) * w2[t];
#pragma unroll
    for (int sh = 16; sh > 0; sh >>= 1) v += __shfl_xor_sync(0xffffffffu, v, sh);
    if ((t & 31) == 0) part[t >> 5] = v;
    __syncthreads();
    if (t == 0) out[g] = part[0] + part[1] + b2[0];
}

// ---------------- launch ----------------
extern "C" void kernel_launch(void* const* d_in, const int* in_sizes, int n_in,
                              void* d_out, int out_size) {
    const float* x        = (const float*)d_in[0];
    const int*   ei       = (const int*)  d_in[1];
    const float* ea       = (const float*)d_in[2];
    const int*   batch    = (const int*)  d_in[3];
    const float* atom_w   = (const float*)d_in[4];
    const float* atom_b   = (const float*)d_in[5];
    const float* e1_w     = (const float*)d_in[6];
    const float* e1_b     = (const float*)d_in[7];
    const float* e2_w     = (const float*)d_in[8];
    const float* e2_b     = (const float*)d_in[9];
    const float* root_w   = (const float*)d_in[10];
    const float* conv_b   = (const float*)d_in[11];
    const float* ln_g     = (const float*)d_in[12];
    const float* ln_b     = (const float*)d_in[13];
    const float* head_w1  = (const float*)d_in[14];
    const float* head_b1  = (const float*)d_in[15];
    const float* head_w2  = (const float*)d_in[16];
    const float* head_b2  = (const float*)d_in[17];
    float* out = (float*)d_out;

    cudaFuncSetAttribute(k_U_mma, cudaFuncAttributeMaxDynamicSharedMemorySize, GEMM_SMEM);
    cudaFuncSetAttribute(k_permW3t, cudaFuncAttributeMaxDynamicSharedMemorySize, PERMW_SMEM);

    dim3 gemm_grid(NN / BM, NCOL / BN + 1);

    // launch index 3 (the ncu capture slot) = layer-0 GEMM
    k_permB3<<<NL * H / 4, 128>>>(e2_b);                                    // 0
    k_permW3t<<<NL * H, 256, PERMW_SMEM>>>(e2_w);                           // 1
    k_atom_split<<<NN, H>>>(x, atom_w, atom_b);                             // 2
    k_U_mma<<<gemm_grid, 128, GEMM_SMEM>>>(0);                              // 3 <- profiled
    k_edge3<<<dim3(NE, NL), H>>>(ea, e1_w, e1_b);                           // 4
    k_prep<<<1, 1024>>>(ei);                                                // 5
    k_msg<<<NN, 128>>>(ei, 0);                                              // 6
    k_update<<<NN, H>>>(root_w, conv_b, ln_g, ln_b);                        // 7

    for (int l = 1; l < NL; l++) {
        k_U_mma<<<gemm_grid, 128, GEMM_SMEM>>>(l);
        k_msg<<<NN, 128>>>(ei, l);
        k_update<<<NN, H>>>(root_w + (size_t)l * H * H, conv_b + (size_t)l * H,
                            ln_g + (size_t)l * H, ln_b + (size_t)l * H);
    }

    k_pool<<<NN, H>>>(batch);
    k_head<<<NGR, 64>>>(head_w1, head_b1, head_w2, head_b2, out);
}

// round 12
// speedup vs baseline: 1.2206x; 1.0285x over previous
#include <cuda_runtime.h>
#include <cuda_bf16.h>
#include <cuda_fp16.h>
#include <math.h>
#include <stdint.h>

#define NN 4096
#define NE 8192
#define NGR 256
#define AF 9
#define BF 4
#define H  128
#define NL 3

#define NCOL (H * H)
#define BM 128
#define BN 128
#define NBROWS (NCOL + H)
#define KA 256
#define KB 256

// ---------------- scratch ----------------
__device__ float g_h[NN * H];
__device__ float g_eh[NL * NE * H];
__device__ __half g_U[(size_t)NN * NCOL];         // compact row space
__device__ float g_nbias[NN * H];                 // compact row space
__device__ float g_agg[NN * H];
__device__ float g_deg[NN];
__device__ float g_mol[NGR * H];
__device__ float g_cnt[NGR];
__device__ __align__(16) __nv_bfloat16 g_A2[(size_t)NN * KA];
__device__ __align__(16) __nv_bfloat16 g_B2[(size_t)NL * NBROWS * KB];
__device__ int g_hist[NN];
__device__ int g_base[NN];
__device__ int g_perm[NE];
__device__ int g_srclist[NN];
__device__ int g_nact;

__device__ __forceinline__ float gelu_exact(float x) {
    return 0.5f * x * (1.0f + erff(x * 0.70710678118654752440f));
}
__device__ __forceinline__ uint32_t smem_u32(const void* p) {
    uint32_t a;
    asm("{ .reg .u64 t; cvta.to.shared.u64 t, %1; cvt.u32.u64 %0, t; }" : "=r"(a) : "l"(p));
    return a;
}

// ---------------- prep: deg + hist + scan + scatter + src compaction ----------------
__global__ __launch_bounds__(1024) void k_prep(const int* __restrict__ ei) {
    __shared__ int cur[NN];
    __shared__ int wsum[32];
    __shared__ int wsum2[32];
    const int t = threadIdx.x;
    for (int n = t; n < NN; n += 1024) { cur[n] = 0; g_deg[n] = 0.f; }
    __syncthreads();
    for (int e = t; e < NE; e += 1024) {
        atomicAdd(&cur[ei[e]], 1);
        atomicAdd(&g_deg[ei[NE + e]], 1.0f);
    }
    __syncthreads();
    const int c0 = cur[4 * t], c1 = cur[4 * t + 1], c2 = cur[4 * t + 2], c3 = cur[4 * t + 3];
    const int s = c0 + c1 + c2 + c3;
    const int a0 = c0 > 0, a1 = c1 > 0, a2 = c2 > 0, a3 = c3 > 0;
    const int as = a0 + a1 + a2 + a3;
    const int lane = t & 31, wid = t >> 5;
    int sc = s, asc = as;
#pragma unroll
    for (int d = 1; d < 32; d <<= 1) {
        int v = __shfl_up_sync(0xffffffffu, sc, d);
        int u = __shfl_up_sync(0xffffffffu, asc, d);
        if (lane >= d) { sc += v; asc += u; }
    }
    if (lane == 31) { wsum[wid] = sc; wsum2[wid] = asc; }
    __syncthreads();
    if (wid == 0) {
        int v = wsum[lane], u = wsum2[lane];
#pragma unroll
        for (int d = 1; d < 32; d <<= 1) {
            int vv = __shfl_up_sync(0xffffffffu, v, d);
            int uu = __shfl_up_sync(0xffffffffu, u, d);
            if (lane >= d) { v += vv; u += uu; }
        }
        wsum[lane] = v; wsum2[lane] = u;
    }
    __syncthreads();
    const int excl = sc - s + (wid ? wsum[wid - 1] : 0);
    const int excl2 = asc - as + (wid ? wsum2[wid - 1] : 0);
    g_hist[4 * t] = c0; g_hist[4 * t + 1] = c1; g_hist[4 * t + 2] = c2; g_hist[4 * t + 3] = c3;
    const int b0 = excl, b1 = b0 + c0, b2 = b1 + c1, b3 = b2 + c2;
    g_base[4 * t] = b0; g_base[4 * t + 1] = b1; g_base[4 * t + 2] = b2; g_base[4 * t + 3] = b3;
    {
        int p = excl2;
        if (a0) g_srclist[p++] = 4 * t;
        if (a1) g_srclist[p++] = 4 * t + 1;
        if (a2) g_srclist[p++] = 4 * t + 2;
        if (a3) g_srclist[p++] = 4 * t + 3;
    }
    if (t == 0) g_nact = wsum2[31];
    __syncthreads();
    const int nact = wsum2[31];
    for (int i = nact + t; i < NN; i += 1024) g_srclist[i] = 0;  // pad rows gather node 0
    cur[4 * t] = b0; cur[4 * t + 1] = b1; cur[4 * t + 2] = b2; cur[4 * t + 3] = b3;
    __syncthreads();
    for (int e = t; e < NE; e += 1024) {
        int pos = atomicAdd(&cur[ei[e]], 1);
        g_perm[pos] = e;
    }
}

// atom embed + split + zero agg/mol/cnt
__global__ void k_atom_split(const float* __restrict__ x, const float* __restrict__ w,
                             const float* __restrict__ b) {
    int n = blockIdx.x, o = threadIdx.x;
    __shared__ float xs[AF];
    if (o < AF) xs[o] = x[n * AF + o];
    g_agg[n * H + o] = 0.f;
    if (n < NGR) g_mol[n * H + o] = 0.f;
    if (n < 2) g_cnt[n * H + o] = 0.f;
    __syncthreads();
    float acc = b[o];
#pragma unroll
    for (int f = 0; f < AF; f++) acc += xs[f] * w[f * H + o];
    float v = fmaxf(acc, 0.f);
    g_h[n * H + o] = v;
    __nv_bfloat16 hi = __float2bfloat16(v);
    g_A2[(size_t)n * KA + o] = hi;
    g_A2[(size_t)n * KA + 128 + o] = __float2bfloat16(v - __bfloat162float(hi));
}

__global__ void k_edge3(const float* __restrict__ ea, const float* __restrict__ w1,
                        const float* __restrict__ b1) {
    int e = blockIdx.x, l = blockIdx.y, o = threadIdx.x;
    __shared__ float es[BF];
    if (o < BF) es[o] = ea[e * BF + o];
    __syncthreads();
    const float* w = w1 + (size_t)l * BF * H;
    float a = b1[l * H + o];
#pragma unroll
    for (int f = 0; f < BF; f++) a += es[f] * w[f * H + o];
    g_eh[(size_t)l * NE * H + e * H + o] = gelu_exact(a);
}

// W2 permute+split via SMEM transpose. One block per (l,j).
__global__ __launch_bounds__(256) void k_permW3t(const float* __restrict__ W2) {
    extern __shared__ float ts[];  // [128][129]
    int bj = blockIdx.x;
    int l = bj >> 7, j = bj & 127;
    const float* src = W2 + ((size_t)l * H + j) * NCOL;
    int tid = threadIdx.x;
    for (int idx = tid; idx < H * H; idx += 256) {
        int i = idx >> 7, o = idx & 127;
        ts[i * 129 + o] = src[idx];
    }
    __syncthreads();
    size_t rowbase = ((size_t)l * NBROWS + (size_t)j * H) * KB;
    for (int idx = tid; idx < H * H; idx += 256) {
        int o = idx >> 7, i = idx & 127;
        float v = ts[i * 129 + o];
        __nv_bfloat16 hi = __float2bfloat16(v);
        g_B2[rowbase + (size_t)o * KB + i] = hi;
        g_B2[rowbase + (size_t)o * KB + 128 + i] = __float2bfloat16(v - __bfloat162float(hi));
    }
}
#define PERMW_SMEM (128 * 129 * 4)

__global__ void k_permB3(const float* __restrict__ e2b) {
    int og = blockIdx.x * 4 + (threadIdx.x >> 5);
    int lid = threadIdx.x & 31;
    int l = og / H, o = og - l * H;
    const float* Bb = e2b + (size_t)l * NCOL;
    size_t base = ((size_t)l * NBROWS + NCOL + o) * KB;
#pragma unroll
    for (int t = 0; t < 4; t++) {
        int i = t * 32 + lid;
        float v = Bb[(size_t)i * H + o];
        __nv_bfloat16 hi = __float2bfloat16(v);
        g_B2[base + i] = hi;
        g_B2[base + 128 + i] = __float2bfloat16(v - __bfloat162float(hi));
    }
}

// ---------------- HMMA GEMM (R7 core) + compact-row gather ----------------
#define SW(row, kb) (((row) * 128 + (kb)) ^ (((row) & 7) << 4))

#define LOAD_TILE_B(slot, gbase, coloff)                                             \
    {                                                                                \
        _Pragma("unroll")                                                            \
        for (int i_ = 0; i_ < 8; i_++) {                                             \
            int cidx = tid + i_ * 128;                                               \
            int row = cidx >> 3, kc = cidx & 7;                                      \
            const void* src = (const char*)(gbase) + (size_t)row * 512 + (coloff) + kc * 16; \
            asm volatile("cp.async.cg.shared.global [%0], [%1], 16;" ::              \
                         "r"(sm + (slot) * 16384 + SW(row, kc * 16)), "l"(src));     \
        }                                                                            \
    }
#define LOAD_TILE_A(slot, coloff)                                                    \
    {                                                                                \
        _Pragma("unroll")                                                            \
        for (int i_ = 0; i_ < 8; i_++) {                                             \
            int cidx = tid + i_ * 128;                                               \
            int row = cidx >> 3, kc = cidx & 7;                                      \
            const void* src = (const char*)g_A2 + (size_t)rowidx[row] * 512 + (coloff) + kc * 16; \
            asm volatile("cp.async.cg.shared.global [%0], [%1], 16;" ::              \
                         "r"(sm + (slot) * 16384 + SW(row, kc * 16)), "l"(src));     \
        }                                                                            \
    }
#define COMMIT() asm volatile("cp.async.commit_group;")
#define WAITSYNC(n) { asm volatile("cp.async.wait_group %0;" :: "n"(n)); __syncthreads(); }

#define COMPUTE(aslot, bslot)                                                        \
    {                                                                                \
        const uint32_t aB = sm + (aslot) * 16384, bB = sm + (bslot) * 16384;         \
        _Pragma("unroll")                                                            \
        for (int ks = 0; ks < 4; ks++) {                                             \
            uint32_t a[4][4];                                                        \
            _Pragma("unroll")                                                        \
            for (int mt = 0; mt < 4; mt++) {                                         \
                int row = wm * 64 + mt * 16 + (lane & 15);                           \
                int kb = ks * 32 + (lane >> 4) * 16;                                 \
                asm volatile("ldmatrix.sync.aligned.m8n8.x4.shared.b16 {%0,%1,%2,%3}, [%4];" \
                             : "=r"(a[mt][0]), "=r"(a[mt][1]), "=r"(a[mt][2]), "=r"(a[mt][3]) \
                             : "r"(aB + SW(row, kb)));                               \
            }                                                                        \
            uint32_t b[4][4];                                                        \
            _Pragma("unroll")                                                        \
            for (int bt = 0; bt < 4; bt++) {                                         \
                int nrow = wn * 64 + bt * 16 + (lane & 7) + ((lane >> 4) & 1) * 8;   \
                int kb = ks * 32 + ((lane >> 3) & 1) * 16;                           \
                asm volatile("ldmatrix.sync.aligned.m8n8.x4.shared.b16 {%0,%1,%2,%3}, [%4];" \
                             : "=r"(b[bt][0]), "=r"(b[bt][1]), "=r"(b[bt][2]), "=r"(b[bt][3]) \
                             : "r"(bB + SW(nrow, kb)));                              \
            }                                                                        \
            _Pragma("unroll")                                                        \
            for (int mt = 0; mt < 4; mt++) {                                         \
                _Pragma("unroll")                                                    \
                for (int nt = 0; nt < 8; nt++) {                                     \
                    asm volatile(                                                    \
                        "mma.sync.aligned.m16n8k16.row.col.f32.bf16.bf16.f32 "       \
                        "{%0,%1,%2,%3}, {%4,%5,%6,%7}, {%8,%9}, {%0,%1,%2,%3};"      \
                        : "+f"(c[mt][nt][0]), "+f"(c[mt][nt][1]),                    \
                          "+f"(c[mt][nt][2]), "+f"(c[mt][nt][3])                     \
                        : "r"(a[mt][0]), "r"(a[mt][1]), "r"(a[mt][2]), "r"(a[mt][3]), \
                          "r"(b[nt >> 1][(nt & 1) * 2]), "r"(b[nt >> 1][(nt & 1) * 2 + 1])); \
                }                                                                    \
            }                                                                        \
        }                                                                            \
    }

__global__ __launch_bounds__(128, 2) void k_U_mma(int l) {
    extern __shared__ char smem[];
    const int tid = threadIdx.x;
    const int m0 = blockIdx.x * BM;
    if (m0 >= g_nact) return;    // compacted: skip inactive m-tiles
    const int warp = tid >> 5, lane = tid & 31;
    const int wm = warp >> 1, wn = warp & 1;
    const int n0 = blockIdx.y * BN;
    const uint32_t sm = smem_u32(smem);
    int* rowidx = (int*)(smem + 98304);

    rowidx[tid] = g_srclist[m0 + tid];
    __syncthreads();

    float c[4][8][4];
#pragma unroll
    for (int mt = 0; mt < 4; mt++)
#pragma unroll
        for (int nt = 0; nt < 8; nt++)
#pragma unroll
            for (int k = 0; k < 4; k++) c[mt][nt][k] = 0.f;

    const char* gB = (const char*)(g_B2 + ((size_t)l * NBROWS + n0) * KB);

    LOAD_TILE_A(0, 0);   LOAD_TILE_B(2, gB, 0);   COMMIT();
    LOAD_TILE_A(1, 128); LOAD_TILE_B(3, gB, 128); COMMIT();
    LOAD_TILE_A(4, 256);                          COMMIT();
    LOAD_TILE_A(5, 384);                          COMMIT();

    WAITSYNC(3); COMPUTE(0, 2);        // Ah0*Bh0
    WAITSYNC(2); COMPUTE(1, 3);        // Ah1*Bh1
    WAITSYNC(1); COMPUTE(4, 2);        // Al0*Bh0
    __syncthreads();
    LOAD_TILE_B(4, gB, 256); COMMIT(); // Bl0->X0
    WAITSYNC(1); COMPUTE(5, 3);        // Al1*Bh1
    __syncthreads();
    LOAD_TILE_B(5, gB, 384); COMMIT(); // Bl1->X1
    WAITSYNC(1); COMPUTE(0, 4);        // Ah0*Bl0
    WAITSYNC(0); COMPUTE(1, 5);        // Ah1*Bl1

    if (blockIdx.y < NCOL / BN) {
#pragma unroll
        for (int mt = 0; mt < 4; mt++) {
            int r0 = m0 + wm * 64 + mt * 16 + (lane >> 2);
#pragma unroll
            for (int nt = 0; nt < 8; nt++) {
                int col = n0 + wn * 64 + nt * 8 + (lane & 3) * 2;
                *(__half2*)(g_U + (size_t)r0 * NCOL + col) =
                    __floats2half2_rn(c[mt][nt][0], c[mt][nt][1]);
                *(__half2*)(g_U + (size_t)(r0 + 8) * NCOL + col) =
                    __floats2half2_rn(c[mt][nt][2], c[mt][nt][3]);
            }
        }
    } else {
#pragma unroll
        for (int mt = 0; mt < 4; mt++) {
            int r0 = m0 + wm * 64 + mt * 16 + (lane >> 2);
#pragma unroll
            for (int nt = 0; nt < 8; nt++) {
                int col = wn * 64 + nt * 8 + (lane & 3) * 2;
                *(float2*)(g_nbias + (size_t)r0 * H + col) = make_float2(c[mt][nt][0], c[mt][nt][1]);
                *(float2*)(g_nbias + (size_t)(r0 + 8) * H + col) = make_float2(c[mt][nt][2], c[mt][nt][3]);
            }
        }
    }
}
#define GEMM_SMEM (98304 + 512)

// per-compact-slot msg: half2 loads, j-range split across thread halves
__global__ __launch_bounds__(128) void k_msg(const int* __restrict__ ei, int l) {
    int b = blockIdx.x;
    if (b >= g_nact) return;
    int n = g_srclist[b];
    int cnt = g_hist[n];
    int base = g_base[n];
    int o = threadIdx.x;
    int half = o >> 6, o2 = o & 63;
    __shared__ float es[4][H];
    __shared__ int dsts[4];
    __shared__ float2 red[4][64];
    const float* ehL = g_eh + (size_t)l * NE * H;
    const float2 nb = *(const float2*)(g_nbias + (size_t)b * H + 2 * o2);
    const __half2* __restrict__ Up2 = (const __half2*)(g_U + (size_t)b * NCOL);

    for (int g0 = 0; g0 < cnt; g0 += 4) {
        int ng = min(4, cnt - g0);
#pragma unroll
        for (int k = 0; k < 4; k++) {
            if (k < ng) {
                int e = g_perm[base + g0 + k];
                es[k][o] = ehL[(size_t)e * H + o];
                if (o == 0) dsts[k] = ei[NE + e];
            } else {
                es[k][o] = 0.f;
            }
        }
        __syncthreads();
        float ax0 = 0.f, ay0 = 0.f, ax1 = 0.f, ay1 = 0.f;
        float ax2 = 0.f, ay2 = 0.f, ax3 = 0.f, ay3 = 0.f;
        const int jb = half * 64;
#pragma unroll 4
        for (int jj = 0; jj < 64; jj++) {
            int j = jb + jj;
            float2 u = __half22float2(Up2[j * 64 + o2]);
            ax0 += es[0][j] * u.x; ay0 += es[0][j] * u.y;
            ax1 += es[1][j] * u.x; ay1 += es[1][j] * u.y;
            ax2 += es[2][j] * u.x; ay2 += es[2][j] * u.y;
            ax3 += es[3][j] * u.x; ay3 += es[3][j] * u.y;
        }
        if (half) {
            red[0][o2] = make_float2(ax0, ay0);
            red[1][o2] = make_float2(ax1, ay1);
            red[2][o2] = make_float2(ax2, ay2);
            red[3][o2] = make_float2(ax3, ay3);
        }
        __syncthreads();
        if (!half) {
            float axs[4] = {ax0, ax1, ax2, ax3};
            float ays[4] = {ay0, ay1, ay2, ay3};
#pragma unroll
            for (int k = 0; k < 4; k++) {
                if (k < ng) {
                    float2 r = red[k][o2];
                    atomicAdd(&g_agg[dsts[k] * H + 2 * o2],     axs[k] + r.x + nb.x);
                    atomicAdd(&g_agg[dsts[k] * H + 2 * o2 + 1], ays[k] + r.y + nb.y);
                }
            }
        }
        __syncthreads();
    }
}

// update + A2 split + agg reset, fused
__global__ void k_update(const float* __restrict__ rootw, const float* __restrict__ convb,
                         const float* __restrict__ lng, const float* __restrict__ lnb) {
    int n = blockIdx.x, o = threadIdx.x;
    __shared__ float hs[H];
    __shared__ float sa[4], sb2[4];
    float hval = g_h[n * H + o];
    hs[o] = hval;
    __syncthreads();
    float r = convb[o];
#pragma unroll 8
    for (int i = 0; i < H; i++) r += hs[i] * rootw[i * H + o];
    float denom = fmaxf(g_deg[n], 1.0f);
    float hn = fmaxf(g_agg[n * H + o] / denom + r, 0.f);
    g_agg[n * H + o] = 0.f;
    float y = hval + hn;

    float s = y, s2 = y * y;
#pragma unroll
    for (int sh = 16; sh > 0; sh >>= 1) {
        s  += __shfl_xor_sync(0xffffffffu, s, sh);
        s2 += __shfl_xor_sync(0xffffffffu, s2, sh);
    }
    int w = o >> 5;
    if ((o & 31) == 0) { sa[w] = s; sb2[w] = s2; }
    __syncthreads();
    float ts = sa[0] + sa[1] + sa[2] + sa[3];
    float ts2 = sb2[0] + sb2[1] + sb2[2] + sb2[3];
    float mu = ts * (1.0f / H);
    float var = ts2 * (1.0f / H) - mu * mu;
    float inv = rsqrtf(var + 1e-5f);
    float v = (y - mu) * inv * lng[o] + lnb[o];
    g_h[n * H + o] = v;
    __nv_bfloat16 hi = __float2bfloat16(v);
    g_A2[(size_t)n * KA + o] = hi;
    g_A2[(size_t)n * KA + 128 + o] = __float2bfloat16(v - __bfloat162float(hi));
}

__global__ void k_pool(const int* __restrict__ batch) {
    int n = blockIdx.x, o = threadIdx.x;
    int b = batch[n];
    atomicAdd(&g_mol[b * H + o], g_h[n * H + o]);
    if (o == 0) atomicAdd(&g_cnt[b], 1.0f);
}

__global__ void k_head(const float* __restrict__ w1, const float* __restrict__ b1,
                       const float* __restrict__ w2, const float* __restrict__ b2,
                       float* __restrict__ out) {
    int g = blockIdx.x, t = threadIdx.x;
    __shared__ float ms[H];
    __shared__ float part[2];
    float inv = 1.0f / fmaxf(g_cnt[g], 1.0f);
    ms[t]      = g_mol[g * H + t] * inv;
    ms[t + 64] = g_mol[g * H + t + 64] * inv;
    __syncthreads();
    float a = b1[t];
#pragma unroll 8
    for (int i = 0; i < H; i++) a += ms[i] * w1[i * 64 + t];
    float v = gelu_exact(a) * w2[t];
#pragma unroll
    for (int sh = 16; sh > 0; sh >>= 1) v += __shfl_xor_sync(0xffffffffu, v, sh);
    if ((t & 31) == 0) part[t >> 5] = v;
    __syncthreads();
    if (t == 0) out[g] = part[0] + part[1] + b2[0];
}

// ---------------- launch ----------------
extern "C" void kernel_launch(void* const* d_in, const int* in_sizes, int n_in,
                              void* d_out, int out_size) {
    const float* x        = (const float*)d_in[0];
    const int*   ei       = (const int*)  d_in[1];
    const float* ea       = (const float*)d_in[2];
    const int*   batch    = (const int*)  d_in[3];
    const float* atom_w   = (const float*)d_in[4];
    const float* atom_b   = (const float*)d_in[5];
    const float* e1_w     = (const float*)d_in[6];
    const float* e1_b     = (const float*)d_in[7];
    const float* e2_w     = (const float*)d_in[8];
    const float* e2_b     = (const float*)d_in[9];
    const float* root_w   = (const float*)d_in[10];
    const float* conv_b   = (const float*)d_in[11];
    const float* ln_g     = (const float*)d_in[12];
    const float* ln_b     = (const float*)d_in[13];
    const float* head_w1  = (const float*)d_in[14];
    const float* head_b1  = (const float*)d_in[15];
    const float* head_w2  = (const float*)d_in[16];
    const float* head_b2  = (const float*)d_in[17];
    float* out = (float*)d_out;

    cudaFuncSetAttribute(k_U_mma, cudaFuncAttributeMaxDynamicSharedMemorySize, GEMM_SMEM);
    cudaFuncSetAttribute(k_permW3t, cudaFuncAttributeMaxDynamicSharedMemorySize, PERMW_SMEM);

    dim3 gemm_grid(NN / BM, NCOL / BN + 1);

    // prep + permB3 + permW3t must all precede the layer-0 GEMM
    k_prep<<<1, 1024>>>(ei);                                                // 0
    k_permB3<<<NL * H / 4, 128>>>(e2_b);                                    // 1
    k_permW3t<<<NL * H, 256, PERMW_SMEM>>>(e2_w);                           // 2
    k_atom_split<<<NN, H>>>(x, atom_w, atom_b);                             // 3
    k_U_mma<<<gemm_grid, 128, GEMM_SMEM>>>(0);                              // 4
    k_edge3<<<dim3(NE, NL), H>>>(ea, e1_w, e1_b);                           // 5
    k_msg<<<NN, 128>>>(ei, 0);                                              // 6
    k_update<<<NN, H>>>(root_w, conv_b, ln_g, ln_b);                        // 7

    for (int l = 1; l < NL; l++) {
        k_U_mma<<<gemm_grid, 128, GEMM_SMEM>>>(l);
        k_msg<<<NN, 128>>>(ei, l);
        k_update<<<NN, H>>>(root_w + (size_t)l * H * H, conv_b + (size_t)l * H,
                            ln_g + (size_t)l * H, ln_b + (size_t)l * H);
    }

    k_pool<<<NN, H>>>(batch);
    k_head<<<NGR, 64>>>(head_w1, head_b1, head_w2, head_b2, out);
}

// round 13
// speedup vs baseline: 1.2564x; 1.0293x over previous
#include <cuda_runtime.h>
#include <cuda_bf16.h>
#include <cuda_fp16.h>
#include <math.h>
#include <stdint.h>

#define NN 4096
#define NE 8192
#define NGR 256
#define AF 9
#define BF 4
#define H  128
#define NL 3

#define NCOL (H * H)
#define BM 128
#define BN 128
#define NBROWS (NCOL + H)
#define KA 256
#define KB 256

// ---------------- scratch ----------------
__device__ float g_h[NN * H];
__device__ float g_eh[NL * NE * H];
__device__ __half g_U[(size_t)NN * NCOL];         // compact row space
__device__ float g_nbias[NN * H];                 // compact row space
__device__ float g_agg[NN * H];
__device__ float g_deg[NN];
__device__ float g_mol[NGR * H];
__device__ float g_cnt[NGR];
__device__ __align__(16) __nv_bfloat16 g_A2[(size_t)NN * KA];
__device__ __align__(16) __nv_bfloat16 g_B2[(size_t)NL * NBROWS * KB];
__device__ int g_hist[NN];
__device__ int g_base[NN];
__device__ int g_perm[NE];
__device__ int g_srclist[NN];
__device__ int g_nact;

__device__ __forceinline__ float gelu_exact(float x) {
    return 0.5f * x * (1.0f + erff(x * 0.70710678118654752440f));
}
__device__ __forceinline__ uint32_t smem_u32(const void* p) {
    uint32_t a;
    asm("{ .reg .u64 t; cvta.to.shared.u64 t, %1; cvt.u32.u64 %0, t; }" : "=r"(a) : "l"(p));
    return a;
}

// ---------------- prep: deg + hist + scan + scatter + src compaction ----------------
__global__ __launch_bounds__(1024) void k_prep(const int* __restrict__ ei) {
    __shared__ int cur[NN];
    __shared__ int wsum[32];
    __shared__ int wsum2[32];
    const int t = threadIdx.x;
    for (int n = t; n < NN; n += 1024) { cur[n] = 0; g_deg[n] = 0.f; }
    __syncthreads();
    for (int e = t; e < NE; e += 1024) {
        atomicAdd(&cur[ei[e]], 1);
        atomicAdd(&g_deg[ei[NE + e]], 1.0f);
    }
    __syncthreads();
    const int c0 = cur[4 * t], c1 = cur[4 * t + 1], c2 = cur[4 * t + 2], c3 = cur[4 * t + 3];
    const int s = c0 + c1 + c2 + c3;
    const int a0 = c0 > 0, a1 = c1 > 0, a2 = c2 > 0, a3 = c3 > 0;
    const int as = a0 + a1 + a2 + a3;
    const int lane = t & 31, wid = t >> 5;
    int sc = s, asc = as;
#pragma unroll
    for (int d = 1; d < 32; d <<= 1) {
        int v = __shfl_up_sync(0xffffffffu, sc, d);
        int u = __shfl_up_sync(0xffffffffu, asc, d);
        if (lane >= d) { sc += v; asc += u; }
    }
    if (lane == 31) { wsum[wid] = sc; wsum2[wid] = asc; }
    __syncthreads();
    if (wid == 0) {
        int v = wsum[lane], u = wsum2[lane];
#pragma unroll
        for (int d = 1; d < 32; d <<= 1) {
            int vv = __shfl_up_sync(0xffffffffu, v, d);
            int uu = __shfl_up_sync(0xffffffffu, u, d);
            if (lane >= d) { v += vv; u += uu; }
        }
        wsum[lane] = v; wsum2[lane] = u;
    }
    __syncthreads();
    const int excl = sc - s + (wid ? wsum[wid - 1] : 0);
    const int excl2 = asc - as + (wid ? wsum2[wid - 1] : 0);
    g_hist[4 * t] = c0; g_hist[4 * t + 1] = c1; g_hist[4 * t + 2] = c2; g_hist[4 * t + 3] = c3;
    const int b0 = excl, b1 = b0 + c0, b2 = b1 + c1, b3 = b2 + c2;
    g_base[4 * t] = b0; g_base[4 * t + 1] = b1; g_base[4 * t + 2] = b2; g_base[4 * t + 3] = b3;
    {
        int p = excl2;
        if (a0) g_srclist[p++] = 4 * t;
        if (a1) g_srclist[p++] = 4 * t + 1;
        if (a2) g_srclist[p++] = 4 * t + 2;
        if (a3) g_srclist[p++] = 4 * t + 3;
    }
    if (t == 0) g_nact = wsum2[31];
    __syncthreads();
    const int nact = wsum2[31];
    for (int i = nact + t; i < NN; i += 1024) g_srclist[i] = 0;  // pad rows gather node 0
    cur[4 * t] = b0; cur[4 * t + 1] = b1; cur[4 * t + 2] = b2; cur[4 * t + 3] = b3;
    __syncthreads();
    for (int e = t; e < NE; e += 1024) {
        int pos = atomicAdd(&cur[ei[e]], 1);
        g_perm[pos] = e;
    }
}

// atom embed + split + zero agg/mol/cnt
__global__ void k_atom_split(const float* __restrict__ x, const float* __restrict__ w,
                             const float* __restrict__ b) {
    int n = blockIdx.x, o = threadIdx.x;
    __shared__ float xs[AF];
    if (o < AF) xs[o] = x[n * AF + o];
    g_agg[n * H + o] = 0.f;
    if (n < NGR) g_mol[n * H + o] = 0.f;
    if (n < 2) g_cnt[n * H + o] = 0.f;
    __syncthreads();
    float acc = b[o];
#pragma unroll
    for (int f = 0; f < AF; f++) acc += xs[f] * w[f * H + o];
    float v = fmaxf(acc, 0.f);
    g_h[n * H + o] = v;
    __nv_bfloat16 hi = __float2bfloat16(v);
    g_A2[(size_t)n * KA + o] = hi;
    g_A2[(size_t)n * KA + 128 + o] = __float2bfloat16(v - __bfloat162float(hi));
}

__global__ void k_edge3(const float* __restrict__ ea, const float* __restrict__ w1,
                        const float* __restrict__ b1) {
    int e = blockIdx.x, l = blockIdx.y, o = threadIdx.x;
    __shared__ float es[BF];
    if (o < BF) es[o] = ea[e * BF + o];
    __syncthreads();
    const float* w = w1 + (size_t)l * BF * H;
    float a = b1[l * H + o];
#pragma unroll
    for (int f = 0; f < BF; f++) a += es[f] * w[f * H + o];
    g_eh[(size_t)l * NE * H + e * H + o] = gelu_exact(a);
}

// merged: W2 permute+split (blocks 0..NL*H-1, SMEM transpose) + bias rows (last 48 blocks)
__global__ __launch_bounds__(256) void k_permWB(const float* __restrict__ W2,
                                                const float* __restrict__ e2b) {
    extern __shared__ float ts[];  // [128][129]
    int bj = blockIdx.x;
    int tid = threadIdx.x;
    if (bj < NL * H) {
        int l = bj >> 7, j = bj & 127;
        const float* src = W2 + ((size_t)l * H + j) * NCOL;
        for (int idx = tid; idx < H * H; idx += 256) {
            int i = idx >> 7, o = idx & 127;
            ts[i * 129 + o] = src[idx];
        }
        __syncthreads();
        size_t rowbase = ((size_t)l * NBROWS + (size_t)j * H) * KB;
        for (int idx = tid; idx < H * H; idx += 256) {
            int o = idx >> 7, i = idx & 127;
            float v = ts[i * 129 + o];
            __nv_bfloat16 hi = __float2bfloat16(v);
            g_B2[rowbase + (size_t)o * KB + i] = hi;
            g_B2[rowbase + (size_t)o * KB + 128 + i] = __float2bfloat16(v - __bfloat162float(hi));
        }
    } else {
        int bb = bj - NL * H;                 // 0..47
        int wrp = tid >> 5, lid = tid & 31;
        int og = bb * 8 + wrp;                // 0..383
        int l = og / H, o = og - l * H;
        const float* Bb = e2b + (size_t)l * NCOL;
        size_t base = ((size_t)l * NBROWS + NCOL + o) * KB;
#pragma unroll
        for (int t = 0; t < 4; t++) {
            int i = t * 32 + lid;
            float v = Bb[(size_t)i * H + o];
            __nv_bfloat16 hi = __float2bfloat16(v);
            g_B2[base + i] = hi;
            g_B2[base + 128 + i] = __float2bfloat16(v - __bfloat162float(hi));
        }
    }
}
#define PERMW_SMEM (128 * 129 * 4)

// ---------------- HMMA GEMM (R7 core) + compact-row gather ----------------
#define SW(row, kb) (((row) * 128 + (kb)) ^ (((row) & 7) << 4))

#define LOAD_TILE_B(slot, gbase, coloff)                                             \
    {                                                                                \
        _Pragma("unroll")                                                            \
        for (int i_ = 0; i_ < 8; i_++) {                                             \
            int cidx = tid + i_ * 128;                                               \
            int row = cidx >> 3, kc = cidx & 7;                                      \
            const void* src = (const char*)(gbase) + (size_t)row * 512 + (coloff) + kc * 16; \
            asm volatile("cp.async.cg.shared.global [%0], [%1], 16;" ::              \
                         "r"(sm + (slot) * 16384 + SW(row, kc * 16)), "l"(src));     \
        }                                                                            \
    }
#define LOAD_TILE_A(slot, coloff)                                                    \
    {                                                                                \
        _Pragma("unroll")                                                            \
        for (int i_ = 0; i_ < 8; i_++) {                                             \
            int cidx = tid + i_ * 128;                                               \
            int row = cidx >> 3, kc = cidx & 7;                                      \
            const void* src = (const char*)g_A2 + (size_t)rowidx[row] * 512 + (coloff) + kc * 16; \
            asm volatile("cp.async.cg.shared.global [%0], [%1], 16;" ::              \
                         "r"(sm + (slot) * 16384 + SW(row, kc * 16)), "l"(src));     \
        }                                                                            \
    }
#define COMMIT() asm volatile("cp.async.commit_group;")
#define WAITSYNC(n) { asm volatile("cp.async.wait_group %0;" :: "n"(n)); __syncthreads(); }

#define COMPUTE(aslot, bslot)                                                        \
    {                                                                                \
        const uint32_t aB = sm + (aslot) * 16384, bB = sm + (bslot) * 16384;         \
        _Pragma("unroll")                                                            \
        for (int ks = 0; ks < 4; ks++) {                                             \
            uint32_t a[4][4];                                                        \
            _Pragma("unroll")                                                        \
            for (int mt = 0; mt < 4; mt++) {                                         \
                int row = wm * 64 + mt * 16 + (lane & 15);                           \
                int kb = ks * 32 + (lane >> 4) * 16;                                 \
                asm volatile("ldmatrix.sync.aligned.m8n8.x4.shared.b16 {%0,%1,%2,%3}, [%4];" \
                             : "=r"(a[mt][0]), "=r"(a[mt][1]), "=r"(a[mt][2]), "=r"(a[mt][3]) \
                             : "r"(aB + SW(row, kb)));                               \
            }                                                                        \
            uint32_t b[4][4];                                                        \
            _Pragma("unroll")                                                        \
            for (int bt = 0; bt < 4; bt++) {                                         \
                int nrow = wn * 64 + bt * 16 + (lane & 7) + ((lane >> 4) & 1) * 8;   \
                int kb = ks * 32 + ((lane >> 3) & 1) * 16;                           \
                asm volatile("ldmatrix.sync.aligned.m8n8.x4.shared.b16 {%0,%1,%2,%3}, [%4];" \
                             : "=r"(b[bt][0]), "=r"(b[bt][1]), "=r"(b[bt][2]), "=r"(b[bt][3]) \
                             : "r"(bB + SW(nrow, kb)));                              \
            }                                                                        \
            _Pragma("unroll")                                                        \
            for (int mt = 0; mt < 4; mt++) {                                         \
                _Pragma("unroll")                                                    \
                for (int nt = 0; nt < 8; nt++) {                                     \
                    asm volatile(                                                    \
                        "mma.sync.aligned.m16n8k16.row.col.f32.bf16.bf16.f32 "       \
                        "{%0,%1,%2,%3}, {%4,%5,%6,%7}, {%8,%9}, {%0,%1,%2,%3};"      \
                        : "+f"(c[mt][nt][0]), "+f"(c[mt][nt][1]),                    \
                          "+f"(c[mt][nt][2]), "+f"(c[mt][nt][3])                     \
                        : "r"(a[mt][0]), "r"(a[mt][1]), "r"(a[mt][2]), "r"(a[mt][3]), \
                          "r"(b[nt >> 1][(nt & 1) * 2]), "r"(b[nt >> 1][(nt & 1) * 2 + 1])); \
                }                                                                    \
            }                                                                        \
        }                                                                            \
    }

__global__ __launch_bounds__(128, 2) void k_U_mma(int l) {
    extern __shared__ char smem[];
    const int tid = threadIdx.x;
    const int m0 = blockIdx.x * BM;
    if (m0 >= g_nact) return;    // compacted: skip inactive m-tiles
    const int warp = tid >> 5, lane = tid & 31;
    const int wm = warp >> 1, wn = warp & 1;
    const int n0 = blockIdx.y * BN;
    const uint32_t sm = smem_u32(smem);
    int* rowidx = (int*)(smem + 98304);

    rowidx[tid] = g_srclist[m0 + tid];
    __syncthreads();

    float c[4][8][4];
#pragma unroll
    for (int mt = 0; mt < 4; mt++)
#pragma unroll
        for (int nt = 0; nt < 8; nt++)
#pragma unroll
            for (int k = 0; k < 4; k++) c[mt][nt][k] = 0.f;

    const char* gB = (const char*)(g_B2 + ((size_t)l * NBROWS + n0) * KB);

    LOAD_TILE_A(0, 0);   LOAD_TILE_B(2, gB, 0);   COMMIT();
    LOAD_TILE_A(1, 128); LOAD_TILE_B(3, gB, 128); COMMIT();
    LOAD_TILE_A(4, 256);                          COMMIT();
    LOAD_TILE_A(5, 384);                          COMMIT();

    WAITSYNC(3); COMPUTE(0, 2);        // Ah0*Bh0
    WAITSYNC(2); COMPUTE(1, 3);        // Ah1*Bh1
    WAITSYNC(1); COMPUTE(4, 2);        // Al0*Bh0
    __syncthreads();
    LOAD_TILE_B(4, gB, 256); COMMIT(); // Bl0->X0
    WAITSYNC(1); COMPUTE(5, 3);        // Al1*Bh1
    __syncthreads();
    LOAD_TILE_B(5, gB, 384); COMMIT(); // Bl1->X1
    WAITSYNC(1); COMPUTE(0, 4);        // Ah0*Bl0
    WAITSYNC(0); COMPUTE(1, 5);        // Ah1*Bl1

    if (blockIdx.y < NCOL / BN) {
#pragma unroll
        for (int mt = 0; mt < 4; mt++) {
            int r0 = m0 + wm * 64 + mt * 16 + (lane >> 2);
#pragma unroll
            for (int nt = 0; nt < 8; nt++) {
                int col = n0 + wn * 64 + nt * 8 + (lane & 3) * 2;
                *(__half2*)(g_U + (size_t)r0 * NCOL + col) =
                    __floats2half2_rn(c[mt][nt][0], c[mt][nt][1]);
                *(__half2*)(g_U + (size_t)(r0 + 8) * NCOL + col) =
                    __floats2half2_rn(c[mt][nt][2], c[mt][nt][3]);
            }
        }
    } else {
#pragma unroll
        for (int mt = 0; mt < 4; mt++) {
            int r0 = m0 + wm * 64 + mt * 16 + (lane >> 2);
#pragma unroll
            for (int nt = 0; nt < 8; nt++) {
                int col = wn * 64 + nt * 8 + (lane & 3) * 2;
                *(float2*)(g_nbias + (size_t)r0 * H + col) = make_float2(c[mt][nt][0], c[mt][nt][1]);
                *(float2*)(g_nbias + (size_t)(r0 + 8) * H + col) = make_float2(c[mt][nt][2], c[mt][nt][3]);
            }
        }
    }
}
#define GEMM_SMEM (98304 + 512)

// per-compact-slot msg: half2 loads, j-range split across thread halves
__global__ __launch_bounds__(128) void k_msg(const int* __restrict__ ei, int l) {
    int b = blockIdx.x;
    if (b >= g_nact) return;
    int n = g_srclist[b];
    int cnt = g_hist[n];
    int base = g_base[n];
    int o = threadIdx.x;
    int half = o >> 6, o2 = o & 63;
    __shared__ float es[4][H];
    __shared__ int dsts[4];
    __shared__ float2 red[4][64];
    const float* ehL = g_eh + (size_t)l * NE * H;
    const float2 nb = *(const float2*)(g_nbias + (size_t)b * H + 2 * o2);
    const __half2* __restrict__ Up2 = (const __half2*)(g_U + (size_t)b * NCOL);

    for (int g0 = 0; g0 < cnt; g0 += 4) {
        int ng = min(4, cnt - g0);
#pragma unroll
        for (int k = 0; k < 4; k++) {
            if (k < ng) {
                int e = g_perm[base + g0 + k];
                es[k][o] = ehL[(size_t)e * H + o];
                if (o == 0) dsts[k] = ei[NE + e];
            } else {
                es[k][o] = 0.f;
            }
        }
        __syncthreads();
        float ax0 = 0.f, ay0 = 0.f, ax1 = 0.f, ay1 = 0.f;
        float ax2 = 0.f, ay2 = 0.f, ax3 = 0.f, ay3 = 0.f;
        const int jb = half * 64;
#pragma unroll 4
        for (int jj = 0; jj < 64; jj++) {
            int j = jb + jj;
            float2 u = __half22float2(Up2[j * 64 + o2]);
            ax0 += es[0][j] * u.x; ay0 += es[0][j] * u.y;
            ax1 += es[1][j] * u.x; ay1 += es[1][j] * u.y;
            ax2 += es[2][j] * u.x; ay2 += es[2][j] * u.y;
            ax3 += es[3][j] * u.x; ay3 += es[3][j] * u.y;
        }
        if (half) {
            red[0][o2] = make_float2(ax0, ay0);
            red[1][o2] = make_float2(ax1, ay1);
            red[2][o2] = make_float2(ax2, ay2);
            red[3][o2] = make_float2(ax3, ay3);
        }
        __syncthreads();
        if (!half) {
            float axs[4] = {ax0, ax1, ax2, ax3};
            float ays[4] = {ay0, ay1, ay2, ay3};
#pragma unroll
            for (int k = 0; k < 4; k++) {
                if (k < ng) {
                    float2 r = red[k][o2];
                    atomicAdd(&g_agg[dsts[k] * H + 2 * o2],     axs[k] + r.x + nb.x);
                    atomicAdd(&g_agg[dsts[k] * H + 2 * o2 + 1], ays[k] + r.y + nb.y);
                }
            }
        }
        __syncthreads();
    }
}

// update + A2 split + agg reset, fused
__global__ void k_update(const float* __restrict__ rootw, const float* __restrict__ convb,
                         const float* __restrict__ lng, const float* __restrict__ lnb) {
    int n = blockIdx.x, o = threadIdx.x;
    __shared__ float hs[H];
    __shared__ float sa[4], sb2[4];
    float hval = g_h[n * H + o];
    hs[o] = hval;
    __syncthreads();
    float r = convb[o];
#pragma unroll 8
    for (int i = 0; i < H; i++) r += hs[i] * rootw[i * H + o];
    float denom = fmaxf(g_deg[n], 1.0f);
    float hn = fmaxf(g_agg[n * H + o] / denom + r, 0.f);
    g_agg[n * H + o] = 0.f;
    float y = hval + hn;

    float s = y, s2 = y * y;
#pragma unroll
    for (int sh = 16; sh > 0; sh >>= 1) {
        s  += __shfl_xor_sync(0xffffffffu, s, sh);
        s2 += __shfl_xor_sync(0xffffffffu, s2, sh);
    }
    int w = o >> 5;
    if ((o & 31) == 0) { sa[w] = s; sb2[w] = s2; }
    __syncthreads();
    float ts = sa[0] + sa[1] + sa[2] + sa[3];
    float ts2 = sb2[0] + sb2[1] + sb2[2] + sb2[3];
    float mu = ts * (1.0f / H);
    float var = ts2 * (1.0f / H) - mu * mu;
    float inv = rsqrtf(var + 1e-5f);
    float v = (y - mu) * inv * lng[o] + lnb[o];
    g_h[n * H + o] = v;
    __nv_bfloat16 hi = __float2bfloat16(v);
    g_A2[(size_t)n * KA + o] = hi;
    g_A2[(size_t)n * KA + 128 + o] = __float2bfloat16(v - __bfloat162float(hi));
}

__global__ void k_pool(const int* __restrict__ batch) {
    int n = blockIdx.x, o = threadIdx.x;
    int b = batch[n];
    atomicAdd(&g_mol[b * H + o], g_h[n * H + o]);
    if (o == 0) atomicAdd(&g_cnt[b], 1.0f);
}

__global__ void k_head(const float* __restrict__ w1, const float* __restrict__ b1,
                       const float* __restrict__ w2, const float* __restrict__ b2,
                       float* __restrict__ out) {
    int g = blockIdx.x, t = threadIdx.x;
    __shared__ float ms[H];
    __shared__ float part[2];
    float inv = 1.0f / fmaxf(g_cnt[g], 1.0f);
    ms[t]      = g_mol[g * H + t] * inv;
    ms[t + 64] = g_mol[g * H + t + 64] * inv;
    __syncthreads();
    float a = b1[t];
#pragma unroll 8
    for (int i = 0; i < H; i++) a += ms[i] * w1[i * 64 + t];
    float v = gelu_exact(a) * w2[t];
#pragma unroll
    for (int sh = 16; sh > 0; sh >>= 1) v += __shfl_xor_sync(0xffffffffu, v, sh);
    if ((t & 31) == 0) part[t >> 5] = v;
    __syncthreads();
    if (t == 0) out[g] = part[0] + part[1] + b2[0];
}

// ---------------- launch ----------------
extern "C" void kernel_launch(void* const* d_in, const int* in_sizes, int n_in,
                              void* d_out, int out_size) {
    const float* x        = (const float*)d_in[0];
    const int*   ei       = (const int*)  d_in[1];
    const float* ea       = (const float*)d_in[2];
    const int*   batch    = (const int*)  d_in[3];
    const float* atom_w   = (const float*)d_in[4];
    const float* atom_b   = (const float*)d_in[5];
    const float* e1_w     = (const float*)d_in[6];
    const float* e1_b     = (const float*)d_in[7];
    const float* e2_w     = (const float*)d_in[8];
    const float* e2_b     = (const float*)d_in[9];
    const float* root_w   = (const float*)d_in[10];
    const float* conv_b   = (const float*)d_in[11];
    const float* ln_g     = (const float*)d_in[12];
    const float* ln_b     = (const float*)d_in[13];
    const float* head_w1  = (const float*)d_in[14];
    const float* head_b1  = (const float*)d_in[15];
    const float* head_w2  = (const float*)d_in[16];
    const float* head_b2  = (const float*)d_in[17];
    float* out = (float*)d_out;

    static cudaStream_t s2 = nullptr;
    static cudaEvent_t evStart = nullptr, evW = nullptr, evE = nullptr;
    if (s2 == nullptr) {
        cudaStreamCreateWithFlags(&s2, cudaStreamNonBlocking);
        cudaEventCreateWithFlags(&evStart, cudaEventDisableTiming);
        cudaEventCreateWithFlags(&evW, cudaEventDisableTiming);
        cudaEventCreateWithFlags(&evE, cudaEventDisableTiming);
        cudaFuncSetAttribute(k_U_mma, cudaFuncAttributeMaxDynamicSharedMemorySize, GEMM_SMEM);
        cudaFuncSetAttribute(k_permWB, cudaFuncAttributeMaxDynamicSharedMemorySize, PERMW_SMEM);
    }

    dim3 gemm_grid(NN / BM, NCOL / BN + 1);

    // fork s2 off the main stream
    cudaEventRecord(evStart, 0);
    cudaStreamWaitEvent(s2, evStart, 0);

    // main stream: prep -> atom -> (wait permWB) -> GEMM0
    k_prep<<<1, 1024>>>(ei);                                                // launch 0
    k_atom_split<<<NN, H>>>(x, atom_w, atom_b);                             // launch 1
    // s2: permWB (B2 for all layers), then edge3 overlapped with GEMM0
    k_permWB<<<NL * H + 48, 256, PERMW_SMEM, s2>>>(e2_w, e2_b);             // launch 2
    cudaEventRecord(evW, s2);
    cudaStreamWaitEvent(0, evW, 0);
    k_U_mma<<<gemm_grid, 128, GEMM_SMEM>>>(0);                              // launch 3 <- profiled
    k_edge3<<<dim3(NE, NL), H, 0, s2>>>(ea, e1_w, e1_b);                    // concurrent with GEMM0
    cudaEventRecord(evE, s2);
    cudaStreamWaitEvent(0, evE, 0);
    k_msg<<<NN, 128>>>(ei, 0);
    k_update<<<NN, H>>>(root_w, conv_b, ln_g, ln_b);

    for (int l = 1; l < NL; l++) {
        k_U_mma<<<gemm_grid, 128, GEMM_SMEM>>>(l);
        k_msg<<<NN, 128>>>(ei, l);
        k_update<<<NN, H>>>(root_w + (size_t)l * H * H, conv_b + (size_t)l * H,
                            ln_g + (size_t)l * H, ln_b + (size_t)l * H);
    }

    k_pool<<<NN, H>>>(batch);
    k_head<<<NGR, 64>>>(head_w1, head_b1, head_w2, head_b2, out);
}

// round 14
// speedup vs baseline: 1.7919x; 1.4262x over previous
#include <cuda_runtime.h>
#include <cuda_bf16.h>
#include <cuda_fp16.h>
#include <math.h>
#include <stdint.h>

#define NN 4096
#define NE 8192
#define NGR 256
#define AF 9
#define BF 4
#define H  128
#define NL 3

#define NCOL (H * H)
#define BM 128
#define BN 128
#define NBROWS (NCOL + H)
#define KA 128                // fp16 single-pass: plain 128-wide rows
#define KB 128

// ---------------- scratch ----------------
__device__ float g_h[NN * H];
__device__ float g_eh[NL * NE * H];
__device__ __half g_U[(size_t)NN * NCOL];         // compact row space
__device__ float g_nbias[NN * H];                 // compact row space
__device__ float g_agg[NN * H];
__device__ float g_deg[NN];
__device__ float g_mol[NGR * H];
__device__ float g_cnt[NGR];
__device__ __align__(16) __half g_A2[(size_t)NN * KA];
__device__ __align__(16) __half g_B2[(size_t)NL * NBROWS * KB];
__device__ int g_hist[NN];
__device__ int g_base[NN];
__device__ int g_perm[NE];
__device__ int g_srclist[NN];
__device__ int g_nact;

__device__ __forceinline__ float gelu_exact(float x) {
    return 0.5f * x * (1.0f + erff(x * 0.70710678118654752440f));
}
__device__ __forceinline__ uint32_t smem_u32(const void* p) {
    uint32_t a;
    asm("{ .reg .u64 t; cvta.to.shared.u64 t, %1; cvt.u32.u64 %0, t; }" : "=r"(a) : "l"(p));
    return a;
}

// ---------------- prep: deg + hist + scan + scatter + src compaction ----------------
__global__ __launch_bounds__(1024) void k_prep(const int* __restrict__ ei) {
    __shared__ int cur[NN];
    __shared__ int wsum[32];
    __shared__ int wsum2[32];
    const int t = threadIdx.x;
    for (int n = t; n < NN; n += 1024) { cur[n] = 0; g_deg[n] = 0.f; }
    __syncthreads();
    for (int e = t; e < NE; e += 1024) {
        atomicAdd(&cur[ei[e]], 1);
        atomicAdd(&g_deg[ei[NE + e]], 1.0f);
    }
    __syncthreads();
    const int c0 = cur[4 * t], c1 = cur[4 * t + 1], c2 = cur[4 * t + 2], c3 = cur[4 * t + 3];
    const int s = c0 + c1 + c2 + c3;
    const int a0 = c0 > 0, a1 = c1 > 0, a2 = c2 > 0, a3 = c3 > 0;
    const int as = a0 + a1 + a2 + a3;
    const int lane = t & 31, wid = t >> 5;
    int sc = s, asc = as;
#pragma unroll
    for (int d = 1; d < 32; d <<= 1) {
        int v = __shfl_up_sync(0xffffffffu, sc, d);
        int u = __shfl_up_sync(0xffffffffu, asc, d);
        if (lane >= d) { sc += v; asc += u; }
    }
    if (lane == 31) { wsum[wid] = sc; wsum2[wid] = asc; }
    __syncthreads();
    if (wid == 0) {
        int v = wsum[lane], u = wsum2[lane];
#pragma unroll
        for (int d = 1; d < 32; d <<= 1) {
            int vv = __shfl_up_sync(0xffffffffu, v, d);
            int uu = __shfl_up_sync(0xffffffffu, u, d);
            if (lane >= d) { v += vv; u += uu; }
        }
        wsum[lane] = v; wsum2[lane] = u;
    }
    __syncthreads();
    const int excl = sc - s + (wid ? wsum[wid - 1] : 0);
    const int excl2 = asc - as + (wid ? wsum2[wid - 1] : 0);
    g_hist[4 * t] = c0; g_hist[4 * t + 1] = c1; g_hist[4 * t + 2] = c2; g_hist[4 * t + 3] = c3;
    const int b0 = excl, b1 = b0 + c0, b2 = b1 + c1, b3 = b2 + c2;
    g_base[4 * t] = b0; g_base[4 * t + 1] = b1; g_base[4 * t + 2] = b2; g_base[4 * t + 3] = b3;
    {
        int p = excl2;
        if (a0) g_srclist[p++] = 4 * t;
        if (a1) g_srclist[p++] = 4 * t + 1;
        if (a2) g_srclist[p++] = 4 * t + 2;
        if (a3) g_srclist[p++] = 4 * t + 3;
    }
    if (t == 0) g_nact = wsum2[31];
    __syncthreads();
    const int nact = wsum2[31];
    for (int i = nact + t; i < NN; i += 1024) g_srclist[i] = 0;  // pad rows gather node 0
    cur[4 * t] = b0; cur[4 * t + 1] = b1; cur[4 * t + 2] = b2; cur[4 * t + 3] = b3;
    __syncthreads();
    for (int e = t; e < NE; e += 1024) {
        int pos = atomicAdd(&cur[ei[e]], 1);
        g_perm[pos] = e;
    }
}

// atom embed + fp16 cast + zero agg/mol/cnt
__global__ void k_atom_split(const float* __restrict__ x, const float* __restrict__ w,
                             const float* __restrict__ b) {
    int n = blockIdx.x, o = threadIdx.x;
    __shared__ float xs[AF];
    if (o < AF) xs[o] = x[n * AF + o];
    g_agg[n * H + o] = 0.f;
    if (n < NGR) g_mol[n * H + o] = 0.f;
    if (n < 2) g_cnt[n * H + o] = 0.f;
    __syncthreads();
    float acc = b[o];
#pragma unroll
    for (int f = 0; f < AF; f++) acc += xs[f] * w[f * H + o];
    float v = fmaxf(acc, 0.f);
    g_h[n * H + o] = v;
    g_A2[(size_t)n * KA + o] = __float2half(v);
}

__global__ void k_edge3(const float* __restrict__ ea, const float* __restrict__ w1,
                        const float* __restrict__ b1) {
    int e = blockIdx.x, l = blockIdx.y, o = threadIdx.x;
    __shared__ float es[BF];
    if (o < BF) es[o] = ea[e * BF + o];
    __syncthreads();
    const float* w = w1 + (size_t)l * BF * H;
    float a = b1[l * H + o];
#pragma unroll
    for (int f = 0; f < BF; f++) a += es[f] * w[f * H + o];
    g_eh[(size_t)l * NE * H + e * H + o] = gelu_exact(a);
}

// merged: W2 permute (blocks 0..NL*H-1, SMEM transpose) + bias rows (last 48 blocks), fp16 out
__global__ __launch_bounds__(256) void k_permWB(const float* __restrict__ W2,
                                                const float* __restrict__ e2b) {
    extern __shared__ float ts[];  // [128][129]
    int bj = blockIdx.x;
    int tid = threadIdx.x;
    if (bj < NL * H) {
        int l = bj >> 7, j = bj & 127;
        const float* src = W2 + ((size_t)l * H + j) * NCOL;
        for (int idx = tid; idx < H * H; idx += 256) {
            int i = idx >> 7, o = idx & 127;
            ts[i * 129 + o] = src[idx];
        }
        __syncthreads();
        size_t rowbase = ((size_t)l * NBROWS + (size_t)j * H) * KB;
        for (int idx = tid; idx < H * H; idx += 256) {
            int o = idx >> 7, i = idx & 127;
            g_B2[rowbase + (size_t)o * KB + i] = __float2half(ts[i * 129 + o]);
        }
    } else {
        int bb = bj - NL * H;                 // 0..47
        int wrp = tid >> 5, lid = tid & 31;
        int og = bb * 8 + wrp;                // 0..383
        int l = og / H, o = og - l * H;
        const float* Bb = e2b + (size_t)l * NCOL;
        size_t base = ((size_t)l * NBROWS + NCOL + o) * KB;
#pragma unroll
        for (int t = 0; t < 4; t++) {
            int i = t * 32 + lid;
            g_B2[base + i] = __float2half(Bb[(size_t)i * H + o]);
        }
    }
}
#define PERMW_SMEM (128 * 129 * 4)

// ---------------- fp16 single-pass HMMA GEMM + compact-row gather ----------------
// Slots (16KB each, 64 k-values per chunk): 0:A0 1:A1 2:B0 3:B1. rowidx at +65536.
#define SW(row, kb) (((row) * 128 + (kb)) ^ (((row) & 7) << 4))

#define LOAD_TILE_B(slot, gbase, coloff)                                             \
    {                                                                                \
        _Pragma("unroll")                                                            \
        for (int i_ = 0; i_ < 8; i_++) {                                             \
            int cidx = tid + i_ * 128;                                               \
            int row = cidx >> 3, kc = cidx & 7;                                      \
            const void* src = (const char*)(gbase) + (size_t)row * 256 + (coloff) + kc * 16; \
            asm volatile("cp.async.cg.shared.global [%0], [%1], 16;" ::              \
                         "r"(sm + (slot) * 16384 + SW(row, kc * 16)), "l"(src));     \
        }                                                                            \
    }
#define LOAD_TILE_A(slot, coloff)                                                    \
    {                                                                                \
        _Pragma("unroll")                                                            \
        for (int i_ = 0; i_ < 8; i_++) {                                             \
            int cidx = tid + i_ * 128;                                               \
            int row = cidx >> 3, kc = cidx & 7;                                      \
            const void* src = (const char*)g_A2 + (size_t)rowidx[row] * 256 + (coloff) + kc * 16; \
            asm volatile("cp.async.cg.shared.global [%0], [%1], 16;" ::              \
                         "r"(sm + (slot) * 16384 + SW(row, kc * 16)), "l"(src));     \
        }                                                                            \
    }
#define COMMIT() asm volatile("cp.async.commit_group;")
#define WAITSYNC(n) { asm volatile("cp.async.wait_group %0;" :: "n"(n)); __syncthreads(); }

#define COMPUTE(aslot, bslot)                                                        \
    {                                                                                \
        const uint32_t aB = sm + (aslot) * 16384, bB = sm + (bslot) * 16384;         \
        _Pragma("unroll")                                                            \
        for (int ks = 0; ks < 4; ks++) {                                             \
            uint32_t a[4][4];                                                        \
            _Pragma("unroll")                                                        \
            for (int mt = 0; mt < 4; mt++) {                                         \
                int row = wm * 64 + mt * 16 + (lane & 15);                           \
                int kb = ks * 32 + (lane >> 4) * 16;                                 \
                asm volatile("ldmatrix.sync.aligned.m8n8.x4.shared.b16 {%0,%1,%2,%3}, [%4];" \
                             : "=r"(a[mt][0]), "=r"(a[mt][1]), "=r"(a[mt][2]), "=r"(a[mt][3]) \
                             : "r"(aB + SW(row, kb)));                               \
            }                                                                        \
            uint32_t b[4][4];                                                        \
            _Pragma("unroll")                                                        \
            for (int bt = 0; bt < 4; bt++) {                                         \
                int nrow = wn * 64 + bt * 16 + (lane & 7) + ((lane >> 4) & 1) * 8;   \
                int kb = ks * 32 + ((lane >> 3) & 1) * 16;                           \
                asm volatile("ldmatrix.sync.aligned.m8n8.x4.shared.b16 {%0,%1,%2,%3}, [%4];" \
                             : "=r"(b[bt][0]), "=r"(b[bt][1]), "=r"(b[bt][2]), "=r"(b[bt][3]) \
                             : "r"(bB + SW(nrow, kb)));                              \
            }                                                                        \
            _Pragma("unroll")                                                        \
            for (int mt = 0; mt < 4; mt++) {                                         \
                _Pragma("unroll")                                                    \
                for (int nt = 0; nt < 8; nt++) {                                     \
                    asm volatile(                                                    \
                        "mma.sync.aligned.m16n8k16.row.col.f32.f16.f16.f32 "         \
                        "{%0,%1,%2,%3}, {%4,%5,%6,%7}, {%8,%9}, {%0,%1,%2,%3};"      \
                        : "+f"(c[mt][nt][0]), "+f"(c[mt][nt][1]),                    \
                          "+f"(c[mt][nt][2]), "+f"(c[mt][nt][3])                     \
                        : "r"(a[mt][0]), "r"(a[mt][1]), "r"(a[mt][2]), "r"(a[mt][3]), \
                          "r"(b[nt >> 1][(nt & 1) * 2]), "r"(b[nt >> 1][(nt & 1) * 2 + 1])); \
                }                                                                    \
            }                                                                        \
        }                                                                            \
    }

__global__ __launch_bounds__(128, 2) void k_U_mma(int l) {
    extern __shared__ char smem[];
    const int tid = threadIdx.x;
    const int m0 = blockIdx.x * BM;
    if (m0 >= g_nact) return;    // compacted: skip inactive m-tiles
    const int warp = tid >> 5, lane = tid & 31;
    const int wm = warp >> 1, wn = warp & 1;
    const int n0 = blockIdx.y * BN;
    const uint32_t sm = smem_u32(smem);
    int* rowidx = (int*)(smem + 65536);

    rowidx[tid] = g_srclist[m0 + tid];
    __syncthreads();

    float c[4][8][4];
#pragma unroll
    for (int mt = 0; mt < 4; mt++)
#pragma unroll
        for (int nt = 0; nt < 8; nt++)
#pragma unroll
            for (int k = 0; k < 4; k++) c[mt][nt][k] = 0.f;

    const char* gB = (const char*)(g_B2 + ((size_t)l * NBROWS + n0) * KB);

    LOAD_TILE_A(0, 0);   LOAD_TILE_B(2, gB, 0);   COMMIT();
    LOAD_TILE_A(1, 128); LOAD_TILE_B(3, gB, 128); COMMIT();

    WAITSYNC(1); COMPUTE(0, 2);        // k = 0..63
    WAITSYNC(0); COMPUTE(1, 3);        // k = 64..127

    if (blockIdx.y < NCOL / BN) {
#pragma unroll
        for (int mt = 0; mt < 4; mt++) {
            int r0 = m0 + wm * 64 + mt * 16 + (lane >> 2);
#pragma unroll
            for (int nt = 0; nt < 8; nt++) {
                int col = n0 + wn * 64 + nt * 8 + (lane & 3) * 2;
                *(__half2*)(g_U + (size_t)r0 * NCOL + col) =
                    __floats2half2_rn(c[mt][nt][0], c[mt][nt][1]);
                *(__half2*)(g_U + (size_t)(r0 + 8) * NCOL + col) =
                    __floats2half2_rn(c[mt][nt][2], c[mt][nt][3]);
            }
        }
    } else {
#pragma unroll
        for (int mt = 0; mt < 4; mt++) {
            int r0 = m0 + wm * 64 + mt * 16 + (lane >> 2);
#pragma unroll
            for (int nt = 0; nt < 8; nt++) {
                int col = wn * 64 + nt * 8 + (lane & 3) * 2;
                *(float2*)(g_nbias + (size_t)r0 * H + col) = make_float2(c[mt][nt][0], c[mt][nt][1]);
                *(float2*)(g_nbias + (size_t)(r0 + 8) * H + col) = make_float2(c[mt][nt][2], c[mt][nt][3]);
            }
        }
    }
}
#define GEMM_SMEM (65536 + 512)

// per-compact-slot msg: half2 loads, j-range split across thread halves
__global__ __launch_bounds__(128) void k_msg(const int* __restrict__ ei, int l) {
    int b = blockIdx.x;
    if (b >= g_nact) return;
    int n = g_srclist[b];
    int cnt = g_hist[n];
    int base = g_base[n];
    int o = threadIdx.x;
    int half = o >> 6, o2 = o & 63;
    __shared__ float es[4][H];
    __shared__ int dsts[4];
    __shared__ float2 red[4][64];
    const float* ehL = g_eh + (size_t)l * NE * H;
    const float2 nb = *(const float2*)(g_nbias + (size_t)b * H + 2 * o2);
    const __half2* __restrict__ Up2 = (const __half2*)(g_U + (size_t)b * NCOL);

    for (int g0 = 0; g0 < cnt; g0 += 4) {
        int ng = min(4, cnt - g0);
#pragma unroll
        for (int k = 0; k < 4; k++) {
            if (k < ng) {
                int e = g_perm[base + g0 + k];
                es[k][o] = ehL[(size_t)e * H + o];
                if (o == 0) dsts[k] = ei[NE + e];
            } else {
                es[k][o] = 0.f;
            }
        }
        __syncthreads();
        float ax0 = 0.f, ay0 = 0.f, ax1 = 0.f, ay1 = 0.f;
        float ax2 = 0.f, ay2 = 0.f, ax3 = 0.f, ay3 = 0.f;
        const int jb = half * 64;
#pragma unroll 4
        for (int jj = 0; jj < 64; jj++) {
            int j = jb + jj;
            float2 u = __half22float2(Up2[j * 64 + o2]);
            ax0 += es[0][j] * u.x; ay0 += es[0][j] * u.y;
            ax1 += es[1][j] * u.x; ay1 += es[1][j] * u.y;
            ax2 += es[2][j] * u.x; ay2 += es[2][j] * u.y;
            ax3 += es[3][j] * u.x; ay3 += es[3][j] * u.y;
        }
        if (half) {
            red[0][o2] = make_float2(ax0, ay0);
            red[1][o2] = make_float2(ax1, ay1);
            red[2][o2] = make_float2(ax2, ay2);
            red[3][o2] = make_float2(ax3, ay3);
        }
        __syncthreads();
        if (!half) {
            float axs[4] = {ax0, ax1, ax2, ax3};
            float ays[4] = {ay0, ay1, ay2, ay3};
#pragma unroll
            for (int k = 0; k < 4; k++) {
                if (k < ng) {
                    float2 r = red[k][o2];
                    atomicAdd(&g_agg[dsts[k] * H + 2 * o2],     axs[k] + r.x + nb.x);
                    atomicAdd(&g_agg[dsts[k] * H + 2 * o2 + 1], ays[k] + r.y + nb.y);
                }
            }
        }
        __syncthreads();
    }
}

// update + fp16 cast + agg reset, fused
__global__ void k_update(const float* __restrict__ rootw, const float* __restrict__ convb,
                         const float* __restrict__ lng, const float* __restrict__ lnb) {
    int n = blockIdx.x, o = threadIdx.x;
    __shared__ float hs[H];
    __shared__ float sa[4], sb2[4];
    float hval = g_h[n * H + o];
    hs[o] = hval;
    __syncthreads();
    float r = convb[o];
#pragma unroll 8
    for (int i = 0; i < H; i++) r += hs[i] * rootw[i * H + o];
    float denom = fmaxf(g_deg[n], 1.0f);
    float hn = fmaxf(g_agg[n * H + o] / denom + r, 0.f);
    g_agg[n * H + o] = 0.f;
    float y = hval + hn;

    float s = y, s2 = y * y;
#pragma unroll
    for (int sh = 16; sh > 0; sh >>= 1) {
        s  += __shfl_xor_sync(0xffffffffu, s, sh);
        s2 += __shfl_xor_sync(0xffffffffu, s2, sh);
    }
    int w = o >> 5;
    if ((o & 31) == 0) { sa[w] = s; sb2[w] = s2; }
    __syncthreads();
    float ts = sa[0] + sa[1] + sa[2] + sa[3];
    float ts2 = sb2[0] + sb2[1] + sb2[2] + sb2[3];
    float mu = ts * (1.0f / H);
    float var = ts2 * (1.0f / H) - mu * mu;
    float inv = rsqrtf(var + 1e-5f);
    float v = (y - mu) * inv * lng[o] + lnb[o];
    g_h[n * H + o] = v;
    g_A2[(size_t)n * KA + o] = __float2half(v);
}

__global__ void k_pool(const int* __restrict__ batch) {
    int n = blockIdx.x, o = threadIdx.x;
    int b = batch[n];
    atomicAdd(&g_mol[b * H + o], g_h[n * H + o]);
    if (o == 0) atomicAdd(&g_cnt[b], 1.0f);
}

__global__ void k_head(const float* __restrict__ w1, const float* __restrict__ b1,
                       const float* __restrict__ w2, const float* __restrict__ b2,
                       float* __restrict__ out) {
    int g = blockIdx.x, t = threadIdx.x;
    __shared__ float ms[H];
    __shared__ float part[2];
    float inv = 1.0f / fmaxf(g_cnt[g], 1.0f);
    ms[t]      = g_mol[g * H + t] * inv;
    ms[t + 64] = g_mol[g * H + t + 64] * inv;
    __syncthreads();
    float a = b1[t];
#pragma unroll 8
    for (int i = 0; i < H; i++) a += ms[i] * w1[i * 64 + t];
    float v = gelu_exact(a) * w2[t];
#pragma unroll
    for (int sh = 16; sh > 0; sh >>= 1) v += __shfl_xor_sync(0xffffffffu, v, sh);
    if ((t & 31) == 0) part[t >> 5] = v;
    __syncthreads();
    if (t == 0) out[g] = part[0] + part[1] + b2[0];
}

// ---------------- launch ----------------
extern "C" void kernel_launch(void* const* d_in, const int* in_sizes, int n_in,
                              void* d_out, int out_size) {
    const float* x        = (const float*)d_in[0];
    const int*   ei       = (const int*)  d_in[1];
    const float* ea       = (const float*)d_in[2];
    const int*   batch    = (const int*)  d_in[3];
    const float* atom_w   = (const float*)d_in[4];
    const float* atom_b   = (const float*)d_in[5];
    const float* e1_w     = (const float*)d_in[6];
    const float* e1_b     = (const float*)d_in[7];
    const float* e2_w     = (const float*)d_in[8];
    const float* e2_b     = (const float*)d_in[9];
    const float* root_w   = (const float*)d_in[10];
    const float* conv_b   = (const float*)d_in[11];
    const float* ln_g     = (const float*)d_in[12];
    const float* ln_b     = (const float*)d_in[13];
    const float* head_w1  = (const float*)d_in[14];
    const float* head_b1  = (const float*)d_in[15];
    const float* head_w2  = (const float*)d_in[16];
    const float* head_b2  = (const float*)d_in[17];
    float* out = (float*)d_out;

    static cudaStream_t s2 = nullptr;
    static cudaEvent_t evStart = nullptr, evW = nullptr, evE = nullptr;
    if (s2 == nullptr) {
        cudaStreamCreateWithFlags(&s2, cudaStreamNonBlocking);
        cudaEventCreateWithFlags(&evStart, cudaEventDisableTiming);
        cudaEventCreateWithFlags(&evW, cudaEventDisableTiming);
        cudaEventCreateWithFlags(&evE, cudaEventDisableTiming);
        cudaFuncSetAttribute(k_U_mma, cudaFuncAttributeMaxDynamicSharedMemorySize, GEMM_SMEM);
        cudaFuncSetAttribute(k_permWB, cudaFuncAttributeMaxDynamicSharedMemorySize, PERMW_SMEM);
    }

    dim3 gemm_grid(NN / BM, NCOL / BN + 1);

    // fork s2 off the main stream
    cudaEventRecord(evStart, 0);
    cudaStreamWaitEvent(s2, evStart, 0);

    // main stream: prep -> atom -> (wait permWB) -> GEMM0
    k_prep<<<1, 1024>>>(ei);                                                // launch 0
    k_atom_split<<<NN, H>>>(x, atom_w, atom_b);                             // launch 1
    // s2: permWB (B2 for all layers), then edge3 overlapped with GEMM0
    k_permWB<<<NL * H + 48, 256, PERMW_SMEM, s2>>>(e2_w, e2_b);             // launch 2
    cudaEventRecord(evW, s2);
    cudaStreamWaitEvent(0, evW, 0);
    k_U_mma<<<gemm_grid, 128, GEMM_SMEM>>>(0);                              // launch 3 <- profiled
    k_edge3<<<dim3(NE, NL), H, 0, s2>>>(ea, e1_w, e1_b);                    // concurrent with GEMM0
    cudaEventRecord(evE, s2);
    cudaStreamWaitEvent(0, evE, 0);
    k_msg<<<NN, 128>>>(ei, 0);
    k_update<<<NN, H>>>(root_w, conv_b, ln_g, ln_b);

    for (int l = 1; l < NL; l++) {
        k_U_mma<<<gemm_grid, 128, GEMM_SMEM>>>(l);
        k_msg<<<NN, 128>>>(ei, l);
        k_update<<<NN, H>>>(root_w + (size_t)l * H * H, conv_b + (size_t)l * H,
                            ln_g + (size_t)l * H, ln_b + (size_t)l * H);
    }

    k_pool<<<NN, H>>>(batch);
    k_head<<<NGR, 64>>>(head_w1, head_b1, head_w2, head_b2, out);
}